// round 5
// baseline (speedup 1.0000x reference)
#include <cuda_runtime.h>
#include <math.h>
#include <stdint.h>

// Problem constants
#define TT 2048
#define BB 2
#define EE 1024
#define HH 8
#define DD 128
#define RR 2
#define CHUNKC 32
#define CC (TT/CHUNKC)   // 64
#define KTOT 1024
#define NTOT 1024

// -------------------- device scratch --------------------
__device__ float g_qf[TT*BB*EE];
__device__ float g_vf[TT*BB*EE];
__device__ float g_ctx[TT*BB*EE];
__device__ float g_invnorm[TT*BB];
__device__ int   g_hash[BB*RR*HH*TT];
__device__ int   g_perm[BB*RR*HH*TT];
__device__ int   g_inv [BB*RR*HH*TT];
__device__ float g_o[RR*BB*HH*TT*DD];
__device__ float g_z[RR*BB*HH*TT];

__device__ __forceinline__ uint32_t f32_to_tf32(float x) {
    uint32_t r; asm("cvt.rna.tf32.f32 %0, %1;" : "=r"(r) : "f"(x)); return r;
}
__device__ __forceinline__ void mma_tf32(float* acc, const uint32_t* a, const uint32_t* b) {
    asm volatile(
        "mma.sync.aligned.m16n8k8.row.col.f32.tf32.tf32.f32 "
        "{%0,%1,%2,%3}, {%4,%5,%6,%7}, {%8,%9}, {%0,%1,%2,%3};"
        : "+f"(acc[0]), "+f"(acc[1]), "+f"(acc[2]), "+f"(acc[3])
        : "r"(a[0]), "r"(a[1]), "r"(a[2]), "r"(a[3]), "r"(b[0]), "r"(b[1]));
}

// ==================== tf32 MMA GEMM: out[M,N] = A[M,K] @ W[K,N] + bias ====================
// CTA tile 128x128, K-step 32, 8 warps (4m x 2n), warp tile 32m x 64n.
// Smem fragment-major layouts: A frag loads = LDS.128, B frag loads = LDS.64.
#define MK 32
#define MNST (KTOT/MK)   // 32
// dynamic smem layout (words): A[2][4096], B[2][4096], bias[128]
#define MM_A(buf)  ((buf)*4096)
#define MM_B(buf)  (8192 + (buf)*4096)
#define MM_BIAS    16384
#define MMA_SMEM   ((16384 + 128) * 4)

__global__ void __launch_bounds__(256, 2) mma_gemm_kernel(
    const float* __restrict__ A, const float* __restrict__ W,
    const float* __restrict__ bias, float* __restrict__ out)
{
    extern __shared__ uint32_t smw[];
    const int tid = threadIdx.x;
    const int lane = tid & 31, wid = tid >> 5;
    const int wm = wid & 3, wn = wid >> 2;
    const int bm = blockIdx.y * 128, bn = blockIdx.x * 128;

    if (tid < 128) ((float*)smw)[MM_BIAS + tid] = bias[bn + tid];

    float acc[2][8][4];
    #pragma unroll
    for (int mt = 0; mt < 2; mt++)
        #pragma unroll
        for (int nt = 0; nt < 8; nt++)
            #pragma unroll
            for (int e = 0; e < 4; e++) acc[mt][nt][e] = 0.f;

    // per-thread fill coordinates
    // A: 4 float4 per thread: idx=tid+i*256, m=idx>>3 (0..127), kq=idx&7
    // B: 4 float4 per thread: idx=tid+i*256, kk=idx>>5 (0..31), n4=idx&31
    float4 pa[4], pb[4];

    #pragma unroll
    for (int i = 0; i < 4; i++) {
        int idx = tid + i*256;
        pa[i] = *(const float4*)&A[(size_t)(bm + (idx>>3))*KTOT + (idx&7)*4];
        pb[i] = *(const float4*)&W[(size_t)(idx>>5)*NTOT + bn + (idx&31)*4];
    }

    // scatter stage 0
    #pragma unroll
    for (int i = 0; i < 4; i++) {
        int idx = tid + i*256;
        {   // A
            int m = idx>>3, kq = idx&7;
            int mtile = m>>4, rr = m&15, g = rr&7, hi = rr>>3;
            float v[4] = {pa[i].x, pa[i].y, pa[i].z, pa[i].w};
            #pragma unroll
            for (int e = 0; e < 4; e++) {
                int k = kq*4 + e, ks = k>>3, cc = k&7, c = cc&3, ch = cc>>2;
                smw[MM_A(0) + ((ks*8 + mtile)*32 + g*4 + c)*4 + hi + ch*2] = f32_to_tf32(v[e]);
            }
        }
        {   // B
            int kk = idx>>5, n4 = idx&31;
            int ks = kk>>3, krel = kk&7, tig = krel&3, half = krel>>2;
            float v[4] = {pb[i].x, pb[i].y, pb[i].z, pb[i].w};
            #pragma unroll
            for (int e = 0; e < 4; e++) {
                int n = n4*4 + e, ntile = n>>3, g = n&7;
                smw[MM_B(0) + ((ks*16 + ntile)*32 + g*4 + tig)*2 + half] = f32_to_tf32(v[e]);
            }
        }
    }
    __syncthreads();

    for (int s = 0; s < MNST; s++) {
        const int buf = s & 1;
        if (s + 1 < MNST) {
            const int k0 = (s + 1) * MK;
            #pragma unroll
            for (int i = 0; i < 4; i++) {
                int idx = tid + i*256;
                pa[i] = *(const float4*)&A[(size_t)(bm + (idx>>3))*KTOT + k0 + (idx&7)*4];
                pb[i] = *(const float4*)&W[(size_t)(k0 + (idx>>5))*NTOT + bn + (idx&31)*4];
            }
        }
        // compute on buf
        #pragma unroll
        for (int ks = 0; ks < 4; ks++) {
            uint32_t afr[2][4], bfr[8][2];
            #pragma unroll
            for (int mt = 0; mt < 2; mt++)
                *(uint4*)afr[mt] = *(const uint4*)&smw[MM_A(buf) + ((ks*8 + wm*2 + mt)*32 + lane)*4];
            #pragma unroll
            for (int nt = 0; nt < 8; nt++)
                *(uint2*)bfr[nt] = *(const uint2*)&smw[MM_B(buf) + ((ks*16 + wn*8 + nt)*32 + lane)*2];
            #pragma unroll
            for (int mt = 0; mt < 2; mt++)
                #pragma unroll
                for (int nt = 0; nt < 8; nt++)
                    mma_tf32(acc[mt][nt], afr[mt], bfr[nt]);
        }
        if (s + 1 < MNST) {
            const int nb = buf ^ 1;
            __syncthreads();
            #pragma unroll
            for (int i = 0; i < 4; i++) {
                int idx = tid + i*256;
                {
                    int m = idx>>3, kq = idx&7;
                    int mtile = m>>4, rr = m&15, g = rr&7, hi = rr>>3;
                    float v[4] = {pa[i].x, pa[i].y, pa[i].z, pa[i].w};
                    #pragma unroll
                    for (int e = 0; e < 4; e++) {
                        int k = kq*4 + e, ks = k>>3, cc = k&7, c = cc&3, ch = cc>>2;
                        smw[MM_A(nb) + ((ks*8 + mtile)*32 + g*4 + c)*4 + hi + ch*2] = f32_to_tf32(v[e]);
                    }
                }
                {
                    int kk = idx>>5, n4 = idx&31;
                    int ks = kk>>3, krel = kk&7, tig = krel&3, half = krel>>2;
                    float v[4] = {pb[i].x, pb[i].y, pb[i].z, pb[i].w};
                    #pragma unroll
                    for (int e = 0; e < 4; e++) {
                        int n = n4*4 + e, ntile = n>>3, g = n&7;
                        smw[MM_B(nb) + ((ks*16 + ntile)*32 + g*4 + tig)*2 + half] = f32_to_tf32(v[e]);
                    }
                }
            }
            __syncthreads();
        }
    }

    // epilogue
    const float* bsm = (const float*)smw + MM_BIAS;
    const int g = lane >> 2, tig = lane & 3;
    #pragma unroll
    for (int mt = 0; mt < 2; mt++) {
        #pragma unroll
        for (int nt = 0; nt < 8; nt++) {
            int m0 = bm + wm*32 + mt*16 + g;
            int nl = wn*64 + nt*8 + tig*2;
            float b0 = bsm[nl], b1 = bsm[nl+1];
            float2 r0 = make_float2(acc[mt][nt][0] + b0, acc[mt][nt][1] + b1);
            float2 r1 = make_float2(acc[mt][nt][2] + b0, acc[mt][nt][3] + b1);
            *(float2*)&out[(size_t)m0*NTOT + bn + nl]       = r0;
            *(float2*)&out[(size_t)(m0+8)*NTOT + bn + nl]   = r1;
        }
    }
}

// ==================== exact FFMA SGEMM (for Wq; hash-sensitive) ====================
#define KS 16
#define NST (KTOT/KS)   // 64

__global__ void __launch_bounds__(256, 2) sgemm_kernel(
    const float* __restrict__ A, const float* __restrict__ W,
    const float* __restrict__ bias, float* __restrict__ out)
{
    __shared__ float As[2][KS][132];
    __shared__ float Bs[2][KS][128];
    __shared__ float bsm[128];

    const int tid = threadIdx.x;
    const int bm = blockIdx.y * 128;
    const int bn = blockIdx.x * 128;
    const int tx = tid & 15;
    const int ty = tid >> 4;

    if (tid < 128) bsm[tid] = bias[bn + tid];

    const int arow = tid >> 2;
    const int akq  = tid & 3;
    const int bkr = tid >> 5;
    const int bn4 = tid & 31;

    const float* Ap0 = A + (size_t)(bm + arow) * KTOT + akq * 4;
    const float* Ap1 = A + (size_t)(bm + 64 + arow) * KTOT + akq * 4;
    const float* Wp0 = W + (size_t)bkr * NTOT + bn + bn4 * 4;
    const float* Wp1 = W + (size_t)(8 + bkr) * NTOT + bn + bn4 * 4;

    float4 pa0, pa1, pb0, pb1;
    float acc[8][8] = {};

    pa0 = *(const float4*)(Ap0);
    pa1 = *(const float4*)(Ap1);
    pb0 = *(const float4*)(Wp0);
    pb1 = *(const float4*)(Wp1);
    {
        const int kb = akq * 4;
        As[0][kb+0][arow]    = pa0.x; As[0][kb+1][arow]    = pa0.y;
        As[0][kb+2][arow]    = pa0.z; As[0][kb+3][arow]    = pa0.w;
        As[0][kb+0][64+arow] = pa1.x; As[0][kb+1][64+arow] = pa1.y;
        As[0][kb+2][64+arow] = pa1.z; As[0][kb+3][64+arow] = pa1.w;
        *(float4*)&Bs[0][bkr][bn4*4]   = pb0;
        *(float4*)&Bs[0][8+bkr][bn4*4] = pb1;
    }
    __syncthreads();

    for (int s = 0; s < NST; s++) {
        const int buf = s & 1;
        if (s + 1 < NST) {
            const size_t ko = (size_t)(s + 1) * KS;
            pa0 = *(const float4*)(Ap0 + ko);
            pa1 = *(const float4*)(Ap1 + ko);
            pb0 = *(const float4*)(Wp0 + ko * NTOT);
            pb1 = *(const float4*)(Wp1 + ko * NTOT);
        }
        #pragma unroll
        for (int k = 0; k < KS; k++) {
            float4 a0 = *(const float4*)&As[buf][k][ty*4];
            float4 a1 = *(const float4*)&As[buf][k][64 + ty*4];
            float4 bv0 = *(const float4*)&Bs[buf][k][tx*4];
            float4 bv1 = *(const float4*)&Bs[buf][k][64 + tx*4];
            float av[8] = {a0.x,a0.y,a0.z,a0.w,a1.x,a1.y,a1.z,a1.w};
            float bw[8] = {bv0.x,bv0.y,bv0.z,bv0.w,bv1.x,bv1.y,bv1.z,bv1.w};
            #pragma unroll
            for (int i = 0; i < 8; i++)
                #pragma unroll
                for (int j = 0; j < 8; j++)
                    acc[i][j] += av[i] * bw[j];
        }
        if (s + 1 < NST) {
            const int nb = buf ^ 1;
            __syncthreads();
            const int kb = akq * 4;
            As[nb][kb+0][arow]    = pa0.x; As[nb][kb+1][arow]    = pa0.y;
            As[nb][kb+2][arow]    = pa0.z; As[nb][kb+3][arow]    = pa0.w;
            As[nb][kb+0][64+arow] = pa1.x; As[nb][kb+1][64+arow] = pa1.y;
            As[nb][kb+2][64+arow] = pa1.z; As[nb][kb+3][64+arow] = pa1.w;
            *(float4*)&Bs[nb][bkr][bn4*4]   = pb0;
            *(float4*)&Bs[nb][8+bkr][bn4*4] = pb1;
            __syncthreads();
        }
    }

    #pragma unroll
    for (int i = 0; i < 8; i++) {
        const int m = bm + ((i < 4) ? (ty*4 + i) : (64 + ty*4 + i - 4));
        float* orow = out + (size_t)m * NTOT + bn;
        const int n0 = tx*4, n1 = 64 + tx*4;
        float4 r0, r1;
        r0.x = acc[i][0] + bsm[n0+0]; r0.y = acc[i][1] + bsm[n0+1];
        r0.z = acc[i][2] + bsm[n0+2]; r0.w = acc[i][3] + bsm[n0+3];
        r1.x = acc[i][4] + bsm[n1+0]; r1.y = acc[i][5] + bsm[n1+1];
        r1.z = acc[i][6] + bsm[n1+2]; r1.w = acc[i][7] + bsm[n1+3];
        *(float4*)(orow + n0) = r0;
        *(float4*)(orow + n1) = r1;
    }
}

// ==================== norm + hash ====================
__global__ void __launch_bounds__(128) norm_hash_kernel(const float* __restrict__ hw)
{
    int tb = blockIdx.x;
    int t = tb >> 1, b = tb & 1;
    const float* row = g_qf + tb*EE;
    int tid = threadIdx.x, lane = tid & 31, wp = tid >> 5;

    float ss = 0.f;
    for (int i = tid; i < EE; i += 128) { float x = row[i]; ss += x*x; }
    #pragma unroll
    for (int o = 16; o; o >>= 1) ss += __shfl_xor_sync(0xffffffffu, ss, o);
    __shared__ float wred[4];
    if (lane == 0) wred[wp] = ss;
    __syncthreads();
    if (tid == 0) g_invnorm[tb] = 1.0f / sqrtf(wred[0]+wred[1]+wred[2]+wred[3]);

    __shared__ float s_lin[64];
    for (int i = 0; i < 16; i++) {
        int co = wp*16 + i;
        int n = co & 3, h = (co >> 2) & 7, r = co >> 5;
        float s = 0.f;
        const float* x = row + h*DD;
        const float* w = hw + ((r*HH + h)*DD)*4 + n;
        for (int d = lane; d < DD; d += 32) s += x[d] * w[d*4];
        #pragma unroll
        for (int o = 16; o; o >>= 1) s += __shfl_xor_sync(0xffffffffu, s, o);
        if (lane == 0) s_lin[co] = s;
    }
    __syncthreads();
    if (tid < 16) {
        int r = tid >> 3, h = tid & 7;
        const float* L = s_lin + (r*8 + h)*4;
        float best = L[0]; int bi = 0;
        #pragma unroll
        for (int j = 1; j < 8; j++) {
            float v = (j < 4) ? L[j] : -L[j-4];
            if (v > best) { best = v; bi = j; }
        }
        g_hash[((b*RR + r)*HH + h)*TT + t] = bi;
    }
}

// ==================== stable counting sort ====================
__global__ void __launch_bounds__(256) sort_kernel()
{
    int brh = blockIdx.x;
    const int* hs = g_hash + brh*TT;
    int* pp = g_perm + brh*TT;
    int* iv = g_inv  + brh*TT;
    __shared__ int hist[256][8];
    __shared__ int binbase[8];
    int tid = threadIdx.x;
    int base = tid*8;
    int myh[8];
    int loc[8] = {0,0,0,0,0,0,0,0};
    #pragma unroll
    for (int i = 0; i < 8; i++) { int v = hs[base+i]; myh[i] = v; loc[v]++; }
    #pragma unroll
    for (int v = 0; v < 8; v++) hist[tid][v] = loc[v];
    __syncthreads();
    if (tid < 8) {
        int s = 0;
        for (int j = 0; j < 256; j++) { int c = hist[j][tid]; hist[j][tid] = s; s += c; }
        binbase[tid] = s;
    }
    __syncthreads();
    if (tid == 0) {
        int s = 0;
        for (int v = 0; v < 8; v++) { int t0 = binbase[v]; binbase[v] = s; s += t0; }
    }
    __syncthreads();
    int off[8];
    #pragma unroll
    for (int v = 0; v < 8; v++) off[v] = binbase[v] + hist[tid][v];
    #pragma unroll
    for (int i = 0; i < 8; i++) {
        int v = myh[i];
        int pos = off[v]++;
        pp[pos] = base + i;
        iv[base + i] = pos;
    }
}

// ==================== chunked LSH attention (register-tiled) ====================
#define QS_STRIDE 132
#define PS_STRIDE 100
#define ATTN_SMEM_FLOATS (32*QS_STRIDE + 96*QS_STRIDE + 96*QS_STRIDE + 32*PS_STRIDE)

__global__ void __launch_bounds__(256) attn_kernel()
{
    extern __shared__ float sm[];
    float* q_s = sm;
    float* k_s = sm + 32*QS_STRIDE;
    float* v_s = k_s + 96*QS_STRIDE;
    float* p_s = v_s + 96*QS_STRIDE;
    __shared__ int s_qid[32], s_kid[96], s_qh[32], s_kh[96];
    __shared__ int s_cq[64], s_ck[192];
    __shared__ float s_kinv[96];

    int bid = blockIdx.x;
    int c = bid & 63;
    int h = (bid >> 6) & 7;
    int r = (bid >> 9) & 1;
    int b = bid >> 10;
    int brh = (b*RR + r)*HH + h;
    const int* pp = g_perm + brh*TT;
    int tid = threadIdx.x, lane = tid & 31, wp = tid >> 5;

    if (tid < 32) {
        int qid = pp[c*32 + tid];
        s_qid[tid] = qid;
        s_qh[tid] = g_hash[brh*TT + qid];
        s_cq[tid*2+0] = g_inv[((b*RR+0)*HH+h)*TT + qid] >> 5;
        s_cq[tid*2+1] = g_inv[((b*RR+1)*HH+h)*TT + qid] >> 5;
    }
    if (tid < 96) {
        int cc = (c + (tid >> 5) + CC - 1) & (CC - 1);
        int kid = pp[cc*32 + (tid & 31)];
        s_kid[tid] = kid;
        s_kh[tid] = g_hash[brh*TT + kid];
        s_kinv[tid] = g_invnorm[kid*BB + b];
        s_ck[tid*2+0] = g_inv[((b*RR+0)*HH+h)*TT + kid] >> 5;
        s_ck[tid*2+1] = g_inv[((b*RR+1)*HH+h)*TT + kid] >> 5;
    }
    __syncthreads();

    const float scale = 0.08838834764831845f;
    for (int idx = tid; idx < 32*32; idx += 256) {
        int l = idx >> 5, d4 = idx & 31;
        float4 v4 = *(const float4*)&g_qf[(s_qid[l]*BB + b)*EE + h*DD + d4*4];
        v4.x *= scale; v4.y *= scale; v4.z *= scale; v4.w *= scale;
        *(float4*)&q_s[l*QS_STRIDE + d4*4] = v4;
    }
    for (int idx = tid; idx < 96*32; idx += 256) {
        int j = idx >> 5, d4 = idx & 31;
        size_t gbase = (size_t)(s_kid[j]*BB + b)*EE + h*DD + d4*4;
        float4 kq = *(const float4*)&g_qf[gbase];
        float4 vv = *(const float4*)&g_vf[gbase];
        float kin = s_kinv[j];
        kq.x *= kin; kq.y *= kin; kq.z *= kin; kq.w *= kin;
        *(float4*)&k_s[j*QS_STRIDE + d4*4] = kq;
        *(float4*)&v_s[j*QS_STRIDE + d4*4] = vv;
    }
    __syncthreads();

    const int l0 = wp*4;

    float acc[4][3] = {};
    {
        const float* kp0 = k_s + lane*QS_STRIDE;
        const float* kp1 = k_s + (lane+32)*QS_STRIDE;
        const float* kp2 = k_s + (lane+64)*QS_STRIDE;
        #pragma unroll 4
        for (int d4 = 0; d4 < 32; d4++) {
            float4 k0 = *(const float4*)(kp0 + d4*4);
            float4 k1 = *(const float4*)(kp1 + d4*4);
            float4 k2 = *(const float4*)(kp2 + d4*4);
            #pragma unroll
            for (int i = 0; i < 4; i++) {
                float4 qv = *(const float4*)&q_s[(l0+i)*QS_STRIDE + d4*4];
                acc[i][0] += qv.x*k0.x; acc[i][0] += qv.y*k0.y;
                acc[i][0] += qv.z*k0.z; acc[i][0] += qv.w*k0.w;
                acc[i][1] += qv.x*k1.x; acc[i][1] += qv.y*k1.y;
                acc[i][1] += qv.z*k1.z; acc[i][1] += qv.w*k1.w;
                acc[i][2] += qv.x*k2.x; acc[i][2] += qv.y*k2.y;
                acc[i][2] += qv.z*k2.z; acc[i][2] += qv.w*k2.w;
            }
        }
    }

    {
        int kh[3], kid[3], ck0[3], ck1[3];
        #pragma unroll
        for (int mi = 0; mi < 3; mi++) {
            int m = mi*32 + lane;
            kh[mi] = s_kh[m]; kid[mi] = s_kid[m];
            ck0[mi] = s_ck[m*2+0]; ck1[mi] = s_ck[m*2+1];
        }
        #pragma unroll
        for (int i = 0; i < 4; i++) {
            int row = l0 + i;
            int qh = s_qh[row], qid = s_qid[row];
            int cq0 = s_cq[row*2], cq1 = s_cq[row*2+1];
            #pragma unroll
            for (int mi = 0; mi < 3; mi++) {
                float s = acc[i][mi];
                if (qh != kh[mi])   s -= 1.0e16f;
                if (qid == kid[mi]) s -= 1.0e8f;
                int d0 = (ck0[mi] - cq0) & (CC-1);
                int d1 = (ck1[mi] - cq1) & (CC-1);
                int dup = ((d0 <= 1) | (d0 == CC-1)) + ((d1 <= 1) | (d1 == CC-1));
                if (dup == 2) s -= 0.6931471805599453f;
                acc[i][mi] = s;
            }
            float mx = fmaxf(acc[i][0], fmaxf(acc[i][1], acc[i][2]));
            #pragma unroll
            for (int o = 16; o; o >>= 1) mx = fmaxf(mx, __shfl_xor_sync(0xffffffffu, mx, o));
            float p0 = expf(acc[i][0]-mx), p1 = expf(acc[i][1]-mx), p2 = expf(acc[i][2]-mx);
            float sum = p0 + p1 + p2;
            #pragma unroll
            for (int o = 16; o; o >>= 1) sum += __shfl_xor_sync(0xffffffffu, sum, o);
            float rinv = 1.0f / sum;
            p_s[row*PS_STRIDE + lane]      = p0*rinv;
            p_s[row*PS_STRIDE + 32 + lane] = p1*rinv;
            p_s[row*PS_STRIDE + 64 + lane] = p2*rinv;
            if (lane == 0) g_z[((r*BB + b)*HH + h)*TT + qid] = logf(sum) + mx;
        }
    }
    __syncwarp();

    float o0x[4], o0y[4], o0z[4], o0w[4];
    #pragma unroll
    for (int i = 0; i < 4; i++) { o0x[i]=0.f; o0y[i]=0.f; o0z[i]=0.f; o0w[i]=0.f; }
    {
        const int dbase = lane*4;
        #pragma unroll 4
        for (int m4 = 0; m4 < 24; m4++) {
            float4 v0 = *(const float4*)&v_s[(m4*4+0)*QS_STRIDE + dbase];
            float4 v1 = *(const float4*)&v_s[(m4*4+1)*QS_STRIDE + dbase];
            float4 v2 = *(const float4*)&v_s[(m4*4+2)*QS_STRIDE + dbase];
            float4 v3 = *(const float4*)&v_s[(m4*4+3)*QS_STRIDE + dbase];
            #pragma unroll
            for (int i = 0; i < 4; i++) {
                float4 pv = *(const float4*)&p_s[(l0+i)*PS_STRIDE + m4*4];
                o0x[i] += pv.x*v0.x; o0y[i] += pv.x*v0.y; o0z[i] += pv.x*v0.z; o0w[i] += pv.x*v0.w;
                o0x[i] += pv.y*v1.x; o0y[i] += pv.y*v1.y; o0z[i] += pv.y*v1.z; o0w[i] += pv.y*v1.w;
                o0x[i] += pv.z*v2.x; o0y[i] += pv.z*v2.y; o0z[i] += pv.z*v2.z; o0w[i] += pv.z*v2.w;
                o0x[i] += pv.w*v3.x; o0y[i] += pv.w*v3.y; o0z[i] += pv.w*v3.z; o0w[i] += pv.w*v3.w;
            }
        }
        #pragma unroll
        for (int i = 0; i < 4; i++) {
            int qid = s_qid[l0+i];
            float* op = g_o + ((size_t)((r*BB + b)*HH + h)*TT + qid)*DD + dbase;
            *(float4*)op = make_float4(o0x[i], o0y[i], o0z[i], o0w[i]);
        }
    }
}

// ==================== round combination ====================
__global__ void __launch_bounds__(256) combine_kernel()
{
    int idx = blockIdx.x*256 + threadIdx.x;
    int d = idx & 127;
    int t = (idx >> 7) & 2047;
    int h = (idx >> 18) & 7;
    int b = idx >> 21;
    int zi = (b*HH + h)*TT + t;
    float z0 = g_z[zi];
    float z1 = g_z[BB*HH*TT + zi];
    float mz = fmaxf(z0, z1);
    float e0 = expf(z0 - mz), e1 = expf(z1 - mz);
    float winv = 1.0f / (e0 + e1);
    int oi = ((b*HH + h)*TT + t)*DD + d;
    float o0 = g_o[oi];
    float o1 = g_o[BB*HH*TT*DD + oi];
    g_ctx[(t*BB + b)*EE + h*DD + d] = (e0*o0 + e1*o1) * winv;
}

// ==================== launch ====================
extern "C" void kernel_launch(void* const* d_in, const int* in_sizes, int n_in,
                              void* d_out, int out_size)
{
    const float* query = (const float*)d_in[0];
    const float* value = (const float*)d_in[2];
    const float* Wq = (const float*)d_in[3];
    const float* bq = (const float*)d_in[4];
    const float* Wv = (const float*)d_in[5];
    const float* bv = (const float*)d_in[6];
    const float* Wo = (const float*)d_in[7];
    const float* bo = (const float*)d_in[8];
    const float* hw = (const float*)d_in[9];

    float* qf;  cudaGetSymbolAddress((void**)&qf,  g_qf);
    float* vf;  cudaGetSymbolAddress((void**)&vf,  g_vf);
    float* ctx; cudaGetSymbolAddress((void**)&ctx, g_ctx);

    const int ATTN_SMEM = ATTN_SMEM_FLOATS * (int)sizeof(float);
    cudaFuncSetAttribute(attn_kernel, cudaFuncAttributeMaxDynamicSharedMemorySize, ATTN_SMEM);
    cudaFuncSetAttribute(mma_gemm_kernel, cudaFuncAttributeMaxDynamicSharedMemorySize, MMA_SMEM);

    dim3 gg(NTOT/128, (TT*BB)/128);   // (8, 32)

    sgemm_kernel<<<gg, 256>>>(query, Wq, bq, qf);                    // exact (hash-sensitive)
    mma_gemm_kernel<<<gg, 256, MMA_SMEM>>>(value, Wv, bv, vf);       // tf32
    norm_hash_kernel<<<TT*BB, 128>>>(hw);
    sort_kernel<<<BB*RR*HH, 256>>>();
    attn_kernel<<<BB*RR*HH*CC, 256, ATTN_SMEM>>>();
    combine_kernel<<<(BB*HH*TT*DD)/256, 256>>>();
    mma_gemm_kernel<<<gg, 256, MMA_SMEM>>>(ctx, Wo, bo, (float*)d_out);  // tf32
}

// round 6
// speedup vs baseline: 1.1482x; 1.1482x over previous
#include <cuda_runtime.h>
#include <math.h>
#include <stdint.h>

// Problem constants
#define TT 2048
#define BB 2
#define EE 1024
#define HH 8
#define DD 128
#define RR 2
#define CHUNKC 32
#define CC (TT/CHUNKC)   // 64
#define KTOT 1024
#define NTOT 1024

// -------------------- device scratch --------------------
__device__ float g_qf[TT*BB*EE];
__device__ float g_vf[TT*BB*EE];
__device__ float g_ctx[TT*BB*EE];
__device__ float g_invnorm[TT*BB];
__device__ int   g_hash[BB*RR*HH*TT];
__device__ int   g_perm[BB*RR*HH*TT];
__device__ int   g_inv [BB*RR*HH*TT];
__device__ float g_o[RR*BB*HH*TT*DD];
__device__ float g_z[RR*BB*HH*TT];

// ==================== exact FFMA SGEMM: out[M,N] = A[M,K] @ W[K,N] + bias ====================
// 128x128 CTA tile, 256 threads, 8x8/thread, K-step 16, double-buffered.
// gridDim.z selects between two problem sets (fused launches).
#define KS 16
#define NST (KTOT/KS)   // 64

__global__ void __launch_bounds__(256, 2) sgemm_kernel(
    const float* __restrict__ A0, const float* __restrict__ W0,
    const float* __restrict__ b0, float* __restrict__ o0,
    const float* __restrict__ A1, const float* __restrict__ W1,
    const float* __restrict__ b1, float* __restrict__ o1)
{
    const float* A    = blockIdx.z ? A1 : A0;
    const float* W    = blockIdx.z ? W1 : W0;
    const float* bias = blockIdx.z ? b1 : b0;
    float*       out  = blockIdx.z ? o1 : o0;

    __shared__ float As[2][KS][132];
    __shared__ float Bs[2][KS][128];
    __shared__ float bsm[128];

    const int tid = threadIdx.x;
    const int bm = blockIdx.y * 128;
    const int bn = blockIdx.x * 128;
    const int tx = tid & 15;
    const int ty = tid >> 4;

    if (tid < 128) bsm[tid] = bias[bn + tid];

    const int arow = tid >> 2;
    const int akq  = tid & 3;
    const int bkr = tid >> 5;
    const int bn4 = tid & 31;

    const float* Ap0 = A + (size_t)(bm + arow) * KTOT + akq * 4;
    const float* Ap1 = A + (size_t)(bm + 64 + arow) * KTOT + akq * 4;
    const float* Wp0 = W + (size_t)bkr * NTOT + bn + bn4 * 4;
    const float* Wp1 = W + (size_t)(8 + bkr) * NTOT + bn + bn4 * 4;

    float4 pa0, pa1, pb0, pb1;
    float acc[8][8] = {};

    pa0 = *(const float4*)(Ap0);
    pa1 = *(const float4*)(Ap1);
    pb0 = *(const float4*)(Wp0);
    pb1 = *(const float4*)(Wp1);
    {
        const int kb = akq * 4;
        As[0][kb+0][arow]    = pa0.x; As[0][kb+1][arow]    = pa0.y;
        As[0][kb+2][arow]    = pa0.z; As[0][kb+3][arow]    = pa0.w;
        As[0][kb+0][64+arow] = pa1.x; As[0][kb+1][64+arow] = pa1.y;
        As[0][kb+2][64+arow] = pa1.z; As[0][kb+3][64+arow] = pa1.w;
        *(float4*)&Bs[0][bkr][bn4*4]   = pb0;
        *(float4*)&Bs[0][8+bkr][bn4*4] = pb1;
    }
    __syncthreads();

    for (int s = 0; s < NST; s++) {
        const int buf = s & 1;
        if (s + 1 < NST) {
            const size_t ko = (size_t)(s + 1) * KS;
            pa0 = *(const float4*)(Ap0 + ko);
            pa1 = *(const float4*)(Ap1 + ko);
            pb0 = *(const float4*)(Wp0 + ko * NTOT);
            pb1 = *(const float4*)(Wp1 + ko * NTOT);
        }
        #pragma unroll
        for (int k = 0; k < KS; k++) {
            float4 a0 = *(const float4*)&As[buf][k][ty*4];
            float4 a1 = *(const float4*)&As[buf][k][64 + ty*4];
            float4 bv0 = *(const float4*)&Bs[buf][k][tx*4];
            float4 bv1 = *(const float4*)&Bs[buf][k][64 + tx*4];
            float av[8] = {a0.x,a0.y,a0.z,a0.w,a1.x,a1.y,a1.z,a1.w};
            float bw[8] = {bv0.x,bv0.y,bv0.z,bv0.w,bv1.x,bv1.y,bv1.z,bv1.w};
            #pragma unroll
            for (int i = 0; i < 8; i++)
                #pragma unroll
                for (int j = 0; j < 8; j++)
                    acc[i][j] += av[i] * bw[j];
        }
        if (s + 1 < NST) {
            const int nb = buf ^ 1;
            __syncthreads();
            const int kb = akq * 4;
            As[nb][kb+0][arow]    = pa0.x; As[nb][kb+1][arow]    = pa0.y;
            As[nb][kb+2][arow]    = pa0.z; As[nb][kb+3][arow]    = pa0.w;
            As[nb][kb+0][64+arow] = pa1.x; As[nb][kb+1][64+arow] = pa1.y;
            As[nb][kb+2][64+arow] = pa1.z; As[nb][kb+3][64+arow] = pa1.w;
            *(float4*)&Bs[nb][bkr][bn4*4]   = pb0;
            *(float4*)&Bs[nb][8+bkr][bn4*4] = pb1;
            __syncthreads();
        }
    }

    #pragma unroll
    for (int i = 0; i < 8; i++) {
        const int m = bm + ((i < 4) ? (ty*4 + i) : (64 + ty*4 + i - 4));
        float* orow = out + (size_t)m * NTOT + bn;
        const int n0 = tx*4, n1 = 64 + tx*4;
        float4 r0, r1;
        r0.x = acc[i][0] + bsm[n0+0]; r0.y = acc[i][1] + bsm[n0+1];
        r0.z = acc[i][2] + bsm[n0+2]; r0.w = acc[i][3] + bsm[n0+3];
        r1.x = acc[i][4] + bsm[n1+0]; r1.y = acc[i][5] + bsm[n1+1];
        r1.z = acc[i][6] + bsm[n1+2]; r1.w = acc[i][7] + bsm[n1+3];
        *(float4*)(orow + n0) = r0;
        *(float4*)(orow + n1) = r1;
    }
}

// ==================== norm + hash ====================
__global__ void __launch_bounds__(128) norm_hash_kernel(const float* __restrict__ hw)
{
    int tb = blockIdx.x;
    int t = tb >> 1, b = tb & 1;
    const float* row = g_qf + tb*EE;
    int tid = threadIdx.x, lane = tid & 31, wp = tid >> 5;

    float ss = 0.f;
    for (int i = tid; i < EE; i += 128) { float x = row[i]; ss += x*x; }
    #pragma unroll
    for (int o = 16; o; o >>= 1) ss += __shfl_xor_sync(0xffffffffu, ss, o);
    __shared__ float wred[4];
    if (lane == 0) wred[wp] = ss;
    __syncthreads();
    if (tid == 0) g_invnorm[tb] = 1.0f / sqrtf(wred[0]+wred[1]+wred[2]+wred[3]);

    __shared__ float s_lin[64];
    for (int i = 0; i < 16; i++) {
        int co = wp*16 + i;
        int n = co & 3, h = (co >> 2) & 7, r = co >> 5;
        float s = 0.f;
        const float* x = row + h*DD;
        const float* w = hw + ((r*HH + h)*DD)*4 + n;
        for (int d = lane; d < DD; d += 32) s += x[d] * w[d*4];
        #pragma unroll
        for (int o = 16; o; o >>= 1) s += __shfl_xor_sync(0xffffffffu, s, o);
        if (lane == 0) s_lin[co] = s;
    }
    __syncthreads();
    if (tid < 16) {
        int r = tid >> 3, h = tid & 7;
        const float* L = s_lin + (r*8 + h)*4;
        float best = L[0]; int bi = 0;
        #pragma unroll
        for (int j = 1; j < 8; j++) {
            float v = (j < 4) ? L[j] : -L[j-4];
            if (v > best) { best = v; bi = j; }
        }
        g_hash[((b*RR + r)*HH + h)*TT + t] = bi;
    }
}

// ==================== stable counting sort ====================
__global__ void __launch_bounds__(256) sort_kernel()
{
    int brh = blockIdx.x;
    const int* hs = g_hash + brh*TT;
    int* pp = g_perm + brh*TT;
    int* iv = g_inv  + brh*TT;
    __shared__ int hist[256][8];
    __shared__ int binbase[8];
    int tid = threadIdx.x;
    int base = tid*8;
    int myh[8];
    int loc[8] = {0,0,0,0,0,0,0,0};
    #pragma unroll
    for (int i = 0; i < 8; i++) { int v = hs[base+i]; myh[i] = v; loc[v]++; }
    #pragma unroll
    for (int v = 0; v < 8; v++) hist[tid][v] = loc[v];
    __syncthreads();
    if (tid < 8) {
        int s = 0;
        for (int j = 0; j < 256; j++) { int c = hist[j][tid]; hist[j][tid] = s; s += c; }
        binbase[tid] = s;
    }
    __syncthreads();
    if (tid == 0) {
        int s = 0;
        for (int v = 0; v < 8; v++) { int t0 = binbase[v]; binbase[v] = s; s += t0; }
    }
    __syncthreads();
    int off[8];
    #pragma unroll
    for (int v = 0; v < 8; v++) off[v] = binbase[v] + hist[tid][v];
    #pragma unroll
    for (int i = 0; i < 8; i++) {
        int v = myh[i];
        int pos = off[v]++;
        pp[pos] = base + i;
        iv[base + i] = pos;
    }
}

// ==================== chunked LSH attention (4 chunks / block) ====================
// Block = (b, r, h, cg) with cg a group of 4 consecutive chunks.
// Window = 6 chunks (192 rows); q rows = window rows 32..159 (q perm == k perm).
// q = k_row * (scale/kinv): no separate q tile. P buffer aliases k_s after QK.
#define QS 132
#define PS 100
#define ATTN_SMEM_BYTES (2*192*QS*4)   // 202752

__global__ void __launch_bounds__(512) attn_kernel()
{
    extern __shared__ float sm[];
    float* k_s = sm;                 // 192 x 132
    float* v_s = sm + 192*QS;        // 192 x 132
    float* p_s = sm;                 // aliases k_s after QK: 128 x 100
    __shared__ int s_kid[192], s_kh[192], s_ck[384];
    __shared__ float s_kinv[192];

    int bid = blockIdx.x;
    int cg = bid & 15;
    int h = (bid >> 4) & 7;
    int r = (bid >> 7) & 1;
    int b = bid >> 8;
    int brh = (b*RR + r)*HH + h;
    const int* pp = g_perm + brh*TT;
    int tid = threadIdx.x, lane = tid & 31, wp = tid >> 5;

    if (tid < 192) {
        int wc = (cg*4 + (tid >> 5) + CC - 1) & (CC - 1);
        int kid = pp[wc*32 + (tid & 31)];
        s_kid[tid] = kid;
        s_kh[tid] = g_hash[brh*TT + kid];
        s_kinv[tid] = g_invnorm[kid*BB + b];
        s_ck[tid*2+0] = g_inv[((b*RR+0)*HH+h)*TT + kid] >> 5;
        s_ck[tid*2+1] = g_inv[((b*RR+1)*HH+h)*TT + kid] >> 5;
    }
    __syncthreads();

    // fill k (normalized) and v tiles: 192 rows x 32 float4
    for (int idx = tid; idx < 192*32; idx += 512) {
        int j = idx >> 5, d4 = idx & 31;
        size_t gbase = (size_t)(s_kid[j]*BB + b)*EE + h*DD + d4*4;
        float4 kq = *(const float4*)&g_qf[gbase];
        float4 vv = *(const float4*)&g_vf[gbase];
        float kin = s_kinv[j];
        kq.x *= kin; kq.y *= kin; kq.z *= kin; kq.w *= kin;
        *(float4*)&k_s[j*QS + d4*4] = kq;
        *(float4*)&v_s[j*QS + d4*4] = vv;
    }
    __syncthreads();

    const int kb = (wp >> 2) * 32;   // key window base for this warp's q-chunk
    const int l0 = wp * 8;           // q rows l0..l0+7 (window rows 32+l)

    // ---------- QK^T over shared k tile
    float acc[8][3];
    #pragma unroll
    for (int i = 0; i < 8; i++) { acc[i][0]=0.f; acc[i][1]=0.f; acc[i][2]=0.f; }
    {
        const float* kp0 = k_s + (kb + lane)*QS;
        const float* kp1 = kp0 + 32*QS;
        const float* kp2 = kp0 + 64*QS;
        const float* qp  = k_s + (32 + l0)*QS;
        #pragma unroll 2
        for (int d4 = 0; d4 < 32; d4++) {
            float4 k0 = *(const float4*)(kp0 + d4*4);
            float4 k1 = *(const float4*)(kp1 + d4*4);
            float4 k2 = *(const float4*)(kp2 + d4*4);
            #pragma unroll
            for (int i = 0; i < 8; i++) {
                float4 qv = *(const float4*)(qp + i*QS + d4*4);
                acc[i][0] += qv.x*k0.x + qv.y*k0.y + qv.z*k0.z + qv.w*k0.w;
                acc[i][1] += qv.x*k1.x + qv.y*k1.y + qv.z*k1.z + qv.w*k1.w;
                acc[i][2] += qv.x*k2.x + qv.y*k2.y + qv.z*k2.z + qv.w*k2.w;
            }
        }
    }

    // ---------- masks + dup correction + softmax (registers only)
    const float scale = 0.08838834764831845f;  // 128^-0.5
    {
        int khv[3], kidv[3], ck0[3], ck1[3];
        #pragma unroll
        for (int mi = 0; mi < 3; mi++) {
            int m = kb + mi*32 + lane;
            khv[mi] = s_kh[m]; kidv[mi] = s_kid[m];
            ck0[mi] = s_ck[m*2+0]; ck1[mi] = s_ck[m*2+1];
        }
        #pragma unroll
        for (int i = 0; i < 8; i++) {
            int row = 32 + l0 + i;              // window index of this q row
            float fq = scale / s_kinv[row];     // q = k_row * fq
            int qh = s_kh[row], qid = s_kid[row];
            int cq0 = s_ck[row*2], cq1 = s_ck[row*2+1];
            #pragma unroll
            for (int mi = 0; mi < 3; mi++) {
                float s = acc[i][mi] * fq;
                if (qh != khv[mi])   s -= 1.0e16f;
                if (qid == kidv[mi]) s -= 1.0e8f;
                int d0 = (ck0[mi] - cq0) & (CC-1);
                int d1 = (ck1[mi] - cq1) & (CC-1);
                int dup = ((d0 <= 1) | (d0 == CC-1)) + ((d1 <= 1) | (d1 == CC-1));
                if (dup == 2) s -= 0.6931471805599453f;
                acc[i][mi] = s;
            }
            float mx = fmaxf(acc[i][0], fmaxf(acc[i][1], acc[i][2]));
            #pragma unroll
            for (int o = 16; o; o >>= 1) mx = fmaxf(mx, __shfl_xor_sync(0xffffffffu, mx, o));
            float p0 = expf(acc[i][0]-mx), p1 = expf(acc[i][1]-mx), p2 = expf(acc[i][2]-mx);
            float sum = p0 + p1 + p2;
            #pragma unroll
            for (int o = 16; o; o >>= 1) sum += __shfl_xor_sync(0xffffffffu, sum, o);
            float rinv = 1.0f / sum;
            acc[i][0] = p0*rinv; acc[i][1] = p1*rinv; acc[i][2] = p2*rinv;
            if (lane == 0) g_z[((r*BB + b)*HH + h)*TT + qid] = logf(sum) + mx;
        }
    }
    __syncthreads();   // all QK reads of k_s done

    // ---------- write P into aliased buffer
    #pragma unroll
    for (int i = 0; i < 8; i++) {
        float* pr = p_s + (l0 + i)*PS;
        pr[lane]      = acc[i][0];
        pr[32 + lane] = acc[i][1];
        pr[64 + lane] = acc[i][2];
    }
    __syncthreads();

    // ---------- P @ V : lane owns d range [lane*4, lane*4+4)
    {
        const int dbase = lane*4;
        float ox[8], oy[8], oz[8], ow[8];
        #pragma unroll
        for (int i = 0; i < 8; i++) { ox[i]=0.f; oy[i]=0.f; oz[i]=0.f; ow[i]=0.f; }
        const float* vb = v_s + kb*QS + dbase;
        #pragma unroll 2
        for (int m4 = 0; m4 < 24; m4++) {
            float4 v0 = *(const float4*)(vb + (m4*4+0)*QS);
            float4 v1 = *(const float4*)(vb + (m4*4+1)*QS);
            float4 v2 = *(const float4*)(vb + (m4*4+2)*QS);
            float4 v3 = *(const float4*)(vb + (m4*4+3)*QS);
            #pragma unroll
            for (int i = 0; i < 8; i++) {
                float4 pv = *(const float4*)&p_s[(l0+i)*PS + m4*4];
                ox[i] += pv.x*v0.x + pv.y*v1.x + pv.z*v2.x + pv.w*v3.x;
                oy[i] += pv.x*v0.y + pv.y*v1.y + pv.z*v2.y + pv.w*v3.y;
                oz[i] += pv.x*v0.z + pv.y*v1.z + pv.z*v2.z + pv.w*v3.z;
                ow[i] += pv.x*v0.w + pv.y*v1.w + pv.z*v2.w + pv.w*v3.w;
            }
        }
        #pragma unroll
        for (int i = 0; i < 8; i++) {
            int qid = s_kid[32 + l0 + i];
            float* op = g_o + ((size_t)((r*BB + b)*HH + h)*TT + qid)*DD + dbase;
            *(float4*)op = make_float4(ox[i], oy[i], oz[i], ow[i]);
        }
    }
}

// ==================== round combination ====================
__global__ void __launch_bounds__(256) combine_kernel()
{
    int idx = blockIdx.x*256 + threadIdx.x;
    int d = idx & 127;
    int t = (idx >> 7) & 2047;
    int h = (idx >> 18) & 7;
    int b = idx >> 21;
    int zi = (b*HH + h)*TT + t;
    float z0 = g_z[zi];
    float z1 = g_z[BB*HH*TT + zi];
    float mz = fmaxf(z0, z1);
    float e0 = expf(z0 - mz), e1 = expf(z1 - mz);
    float winv = 1.0f / (e0 + e1);
    int oi = ((b*HH + h)*TT + t)*DD + d;
    float o0 = g_o[oi];
    float o1 = g_o[BB*HH*TT*DD + oi];
    g_ctx[(t*BB + b)*EE + h*DD + d] = (e0*o0 + e1*o1) * winv;
}

// ==================== launch ====================
extern "C" void kernel_launch(void* const* d_in, const int* in_sizes, int n_in,
                              void* d_out, int out_size)
{
    const float* query = (const float*)d_in[0];
    const float* value = (const float*)d_in[2];
    const float* Wq = (const float*)d_in[3];
    const float* bq = (const float*)d_in[4];
    const float* Wv = (const float*)d_in[5];
    const float* bv = (const float*)d_in[6];
    const float* Wo = (const float*)d_in[7];
    const float* bo = (const float*)d_in[8];
    const float* hw = (const float*)d_in[9];

    float* qf;  cudaGetSymbolAddress((void**)&qf,  g_qf);
    float* vf;  cudaGetSymbolAddress((void**)&vf,  g_vf);
    float* ctx; cudaGetSymbolAddress((void**)&ctx, g_ctx);

    cudaFuncSetAttribute(attn_kernel, cudaFuncAttributeMaxDynamicSharedMemorySize, ATTN_SMEM_BYTES);

    dim3 gqv(NTOT/128, (TT*BB)/128, 2);   // fused Wq + Wv projections
    dim3 go (NTOT/128, (TT*BB)/128, 1);   // Wo projection

    sgemm_kernel<<<gqv, 256>>>(query, Wq, bq, qf, value, Wv, bv, vf);
    norm_hash_kernel<<<TT*BB, 128>>>(hw);
    sort_kernel<<<BB*RR*HH, 256>>>();
    attn_kernel<<<BB*RR*HH*16, 512, ATTN_SMEM_BYTES>>>();
    combine_kernel<<<(BB*HH*TT*DD)/256, 256>>>();
    sgemm_kernel<<<go, 256>>>(ctx, Wo, bo, (float*)d_out,
                              ctx, Wo, bo, (float*)d_out);
}

// round 7
// speedup vs baseline: 1.2597x; 1.0971x over previous
#include <cuda_runtime.h>
#include <math.h>
#include <stdint.h>

// Problem constants
#define TT 2048
#define BB 2
#define EE 1024
#define HH 8
#define DD 128
#define RR 2
#define CHUNKC 32
#define CC (TT/CHUNKC)   // 64
#define KTOT 1024
#define NTOT 1024

typedef unsigned long long u64;

// packed f32x2 helpers (sm_100+ PTX; ptxas never auto-fuses these)
#define FMA2(acc, x, y) \
    asm("fma.rn.f32x2 %0, %1, %2, %0;" : "+l"(acc) : "l"(x), "l"(y))
#define SPLAT2(d, s) \
    asm("mov.b64 %0, {%1, %1};" : "=l"(d) : "r"(s))

__device__ __forceinline__ float lo_f(u64 v) { return __uint_as_float((uint32_t)v); }
__device__ __forceinline__ float hi_f(u64 v) { return __uint_as_float((uint32_t)(v >> 32)); }

// -------------------- device scratch --------------------
__device__ float g_qf[TT*BB*EE];
__device__ float g_vf[TT*BB*EE];
__device__ float g_ctx[TT*BB*EE];
__device__ float g_invnorm[TT*BB];
__device__ int   g_hash[BB*RR*HH*TT];
__device__ int   g_perm[BB*RR*HH*TT];
__device__ int   g_inv [BB*RR*HH*TT];
__device__ float g_o[RR*BB*HH*TT*DD];
__device__ float g_z[RR*BB*HH*TT];

// ==================== exact-fp32 SGEMM (f32x2): out = A @ W + bias ====================
// 128x128 CTA tile, 256 threads, 8x8/thread (as 4 m-pairs x 8 n), K-step 16.
#define KS 16
#define NST (KTOT/KS)   // 64

__global__ void __launch_bounds__(256, 2) sgemm_kernel(
    const float* __restrict__ A0, const float* __restrict__ W0,
    const float* __restrict__ b0, float* __restrict__ o0,
    const float* __restrict__ A1, const float* __restrict__ W1,
    const float* __restrict__ b1, float* __restrict__ o1)
{
    const float* A    = blockIdx.z ? A1 : A0;
    const float* W    = blockIdx.z ? W1 : W0;
    const float* bias = blockIdx.z ? b1 : b0;
    float*       out  = blockIdx.z ? o1 : o0;

    __shared__ __align__(16) float As[2][KS][132];
    __shared__ __align__(16) float Bs[2][KS][128];
    __shared__ float bsm[128];

    const int tid = threadIdx.x;
    const int bm = blockIdx.y * 128;
    const int bn = blockIdx.x * 128;
    const int tx = tid & 15;
    const int ty = tid >> 4;

    if (tid < 128) bsm[tid] = bias[bn + tid];

    const int arow = tid >> 2;
    const int akq  = tid & 3;
    const int bkr = tid >> 5;
    const int bn4 = tid & 31;

    const float* Ap0 = A + (size_t)(bm + arow) * KTOT + akq * 4;
    const float* Ap1 = A + (size_t)(bm + 64 + arow) * KTOT + akq * 4;
    const float* Wp0 = W + (size_t)bkr * NTOT + bn + bn4 * 4;
    const float* Wp1 = W + (size_t)(8 + bkr) * NTOT + bn + bn4 * 4;

    float4 pa0, pa1, pb0, pb1;
    u64 acc2[4][8];
    #pragma unroll
    for (int i = 0; i < 4; i++)
        #pragma unroll
        for (int j = 0; j < 8; j++) acc2[i][j] = 0ull;

    pa0 = *(const float4*)(Ap0);
    pa1 = *(const float4*)(Ap1);
    pb0 = *(const float4*)(Wp0);
    pb1 = *(const float4*)(Wp1);
    {
        const int kb = akq * 4;
        As[0][kb+0][arow]    = pa0.x; As[0][kb+1][arow]    = pa0.y;
        As[0][kb+2][arow]    = pa0.z; As[0][kb+3][arow]    = pa0.w;
        As[0][kb+0][64+arow] = pa1.x; As[0][kb+1][64+arow] = pa1.y;
        As[0][kb+2][64+arow] = pa1.z; As[0][kb+3][64+arow] = pa1.w;
        *(float4*)&Bs[0][bkr][bn4*4]   = pb0;
        *(float4*)&Bs[0][8+bkr][bn4*4] = pb1;
    }
    __syncthreads();

    for (int s = 0; s < NST; s++) {
        const int buf = s & 1;
        if (s + 1 < NST) {
            const size_t ko = (size_t)(s + 1) * KS;
            pa0 = *(const float4*)(Ap0 + ko);
            pa1 = *(const float4*)(Ap1 + ko);
            pb0 = *(const float4*)(Wp0 + ko * NTOT);
            pb1 = *(const float4*)(Wp1 + ko * NTOT);
        }
        #pragma unroll
        for (int k = 0; k < KS; k++) {
            ulonglong2 a0 = *(const ulonglong2*)&As[buf][k][ty*4];
            ulonglong2 a1 = *(const ulonglong2*)&As[buf][k][64 + ty*4];
            float4 bv0 = *(const float4*)&Bs[buf][k][tx*4];
            float4 bv1 = *(const float4*)&Bs[buf][k][64 + tx*4];
            u64 ap[4] = {a0.x, a0.y, a1.x, a1.y};
            u64 bs2[8];
            SPLAT2(bs2[0], __float_as_uint(bv0.x));
            SPLAT2(bs2[1], __float_as_uint(bv0.y));
            SPLAT2(bs2[2], __float_as_uint(bv0.z));
            SPLAT2(bs2[3], __float_as_uint(bv0.w));
            SPLAT2(bs2[4], __float_as_uint(bv1.x));
            SPLAT2(bs2[5], __float_as_uint(bv1.y));
            SPLAT2(bs2[6], __float_as_uint(bv1.z));
            SPLAT2(bs2[7], __float_as_uint(bv1.w));
            #pragma unroll
            for (int i = 0; i < 4; i++)
                #pragma unroll
                for (int j = 0; j < 8; j++)
                    FMA2(acc2[i][j], ap[i], bs2[j]);
        }
        if (s + 1 < NST) {
            const int nb = buf ^ 1;
            __syncthreads();
            const int kb = akq * 4;
            As[nb][kb+0][arow]    = pa0.x; As[nb][kb+1][arow]    = pa0.y;
            As[nb][kb+2][arow]    = pa0.z; As[nb][kb+3][arow]    = pa0.w;
            As[nb][kb+0][64+arow] = pa1.x; As[nb][kb+1][64+arow] = pa1.y;
            As[nb][kb+2][64+arow] = pa1.z; As[nb][kb+3][64+arow] = pa1.w;
            *(float4*)&Bs[nb][bkr][bn4*4]   = pb0;
            *(float4*)&Bs[nb][8+bkr][bn4*4] = pb1;
            __syncthreads();
        }
    }

    // epilogue: m-pair i2 -> rows (base, base+1)
    #pragma unroll
    for (int i2 = 0; i2 < 4; i2++) {
        const int mrow = bm + ((i2 < 2) ? (ty*4 + i2*2) : (64 + ty*4 + (i2-2)*2));
        const int n0 = tx*4, n1 = 64 + tx*4;
        float* r0 = out + (size_t)mrow * NTOT + bn;
        float* r1 = out + (size_t)(mrow+1) * NTOT + bn;
        float4 lo0, lo1, hi0, hi1;
        lo0.x = lo_f(acc2[i2][0]) + bsm[n0+0]; hi0.x = hi_f(acc2[i2][0]) + bsm[n0+0];
        lo0.y = lo_f(acc2[i2][1]) + bsm[n0+1]; hi0.y = hi_f(acc2[i2][1]) + bsm[n0+1];
        lo0.z = lo_f(acc2[i2][2]) + bsm[n0+2]; hi0.z = hi_f(acc2[i2][2]) + bsm[n0+2];
        lo0.w = lo_f(acc2[i2][3]) + bsm[n0+3]; hi0.w = hi_f(acc2[i2][3]) + bsm[n0+3];
        lo1.x = lo_f(acc2[i2][4]) + bsm[n1+0]; hi1.x = hi_f(acc2[i2][4]) + bsm[n1+0];
        lo1.y = lo_f(acc2[i2][5]) + bsm[n1+1]; hi1.y = hi_f(acc2[i2][5]) + bsm[n1+1];
        lo1.z = lo_f(acc2[i2][6]) + bsm[n1+2]; hi1.z = hi_f(acc2[i2][6]) + bsm[n1+2];
        lo1.w = lo_f(acc2[i2][7]) + bsm[n1+3]; hi1.w = hi_f(acc2[i2][7]) + bsm[n1+3];
        *(float4*)(r0 + n0) = lo0;
        *(float4*)(r0 + n1) = lo1;
        *(float4*)(r1 + n0) = hi0;
        *(float4*)(r1 + n1) = hi1;
    }
}

// ==================== norm + hash ====================
__global__ void __launch_bounds__(128) norm_hash_kernel(const float* __restrict__ hw)
{
    int tb = blockIdx.x;
    int t = tb >> 1, b = tb & 1;
    const float* row = g_qf + tb*EE;
    int tid = threadIdx.x, lane = tid & 31, wp = tid >> 5;

    float ss = 0.f;
    for (int i = tid; i < EE; i += 128) { float x = row[i]; ss += x*x; }
    #pragma unroll
    for (int o = 16; o; o >>= 1) ss += __shfl_xor_sync(0xffffffffu, ss, o);
    __shared__ float wred[4];
    if (lane == 0) wred[wp] = ss;
    __syncthreads();
    if (tid == 0) g_invnorm[tb] = 1.0f / sqrtf(wred[0]+wred[1]+wred[2]+wred[3]);

    __shared__ float s_lin[64];
    for (int i = 0; i < 16; i++) {
        int co = wp*16 + i;
        int n = co & 3, h = (co >> 2) & 7, r = co >> 5;
        float s = 0.f;
        const float* x = row + h*DD;
        const float* w = hw + ((r*HH + h)*DD)*4 + n;
        for (int d = lane; d < DD; d += 32) s += x[d] * w[d*4];
        #pragma unroll
        for (int o = 16; o; o >>= 1) s += __shfl_xor_sync(0xffffffffu, s, o);
        if (lane == 0) s_lin[co] = s;
    }
    __syncthreads();
    if (tid < 16) {
        int r = tid >> 3, h = tid & 7;
        const float* L = s_lin + (r*8 + h)*4;
        float best = L[0]; int bi = 0;
        #pragma unroll
        for (int j = 1; j < 8; j++) {
            float v = (j < 4) ? L[j] : -L[j-4];
            if (v > best) { best = v; bi = j; }
        }
        g_hash[((b*RR + r)*HH + h)*TT + t] = bi;
    }
}

// ==================== stable counting sort ====================
__global__ void __launch_bounds__(256) sort_kernel()
{
    int brh = blockIdx.x;
    const int* hs = g_hash + brh*TT;
    int* pp = g_perm + brh*TT;
    int* iv = g_inv  + brh*TT;
    __shared__ int hist[256][8];
    __shared__ int binbase[8];
    int tid = threadIdx.x;
    int base = tid*8;
    int myh[8];
    int loc[8] = {0,0,0,0,0,0,0,0};
    #pragma unroll
    for (int i = 0; i < 8; i++) { int v = hs[base+i]; myh[i] = v; loc[v]++; }
    #pragma unroll
    for (int v = 0; v < 8; v++) hist[tid][v] = loc[v];
    __syncthreads();
    if (tid < 8) {
        int s = 0;
        for (int j = 0; j < 256; j++) { int c = hist[j][tid]; hist[j][tid] = s; s += c; }
        binbase[tid] = s;
    }
    __syncthreads();
    if (tid == 0) {
        int s = 0;
        for (int v = 0; v < 8; v++) { int t0 = binbase[v]; binbase[v] = s; s += t0; }
    }
    __syncthreads();
    int off[8];
    #pragma unroll
    for (int v = 0; v < 8; v++) off[v] = binbase[v] + hist[tid][v];
    #pragma unroll
    for (int i = 0; i < 8; i++) {
        int v = myh[i];
        int pos = off[v]++;
        pp[pos] = base + i;
        iv[base + i] = pos;
    }
}

// ==================== chunked LSH attention (4 chunks / block, f32x2) ====================
#define QS 132
#define PS 100
#define ATTN_SMEM_BYTES (2*192*QS*4)   // 202752

__global__ void __launch_bounds__(512) attn_kernel()
{
    extern __shared__ float sm[];
    float* k_s = sm;                 // 192 x 132
    float* v_s = sm + 192*QS;        // 192 x 132
    float* p_s = sm;                 // aliases k_s after QK: 128 x 100
    __shared__ int s_kid[192], s_kh[192], s_ck[384];
    __shared__ float s_kinv[192];

    int bid = blockIdx.x;
    int cg = bid & 15;
    int h = (bid >> 4) & 7;
    int r = (bid >> 7) & 1;
    int b = bid >> 8;
    int brh = (b*RR + r)*HH + h;
    const int* pp = g_perm + brh*TT;
    int tid = threadIdx.x, lane = tid & 31, wp = tid >> 5;

    if (tid < 192) {
        int wc = (cg*4 + (tid >> 5) + CC - 1) & (CC - 1);
        int kid = pp[wc*32 + (tid & 31)];
        s_kid[tid] = kid;
        s_kh[tid] = g_hash[brh*TT + kid];
        s_kinv[tid] = g_invnorm[kid*BB + b];
        s_ck[tid*2+0] = g_inv[((b*RR+0)*HH+h)*TT + kid] >> 5;
        s_ck[tid*2+1] = g_inv[((b*RR+1)*HH+h)*TT + kid] >> 5;
    }
    __syncthreads();

    for (int idx = tid; idx < 192*32; idx += 512) {
        int j = idx >> 5, d4 = idx & 31;
        size_t gbase = (size_t)(s_kid[j]*BB + b)*EE + h*DD + d4*4;
        float4 kq = *(const float4*)&g_qf[gbase];
        float4 vv = *(const float4*)&g_vf[gbase];
        float kin = s_kinv[j];
        kq.x *= kin; kq.y *= kin; kq.z *= kin; kq.w *= kin;
        *(float4*)&k_s[j*QS + d4*4] = kq;
        *(float4*)&v_s[j*QS + d4*4] = vv;
    }
    __syncthreads();

    const int kb = (wp >> 2) * 32;
    const int l0 = wp * 8;

    // ---------- QK^T (packed along d)
    u64 acc2[8][3];
    #pragma unroll
    for (int i = 0; i < 8; i++) { acc2[i][0]=0ull; acc2[i][1]=0ull; acc2[i][2]=0ull; }
    {
        const float* kp0 = k_s + (kb + lane)*QS;
        const float* kp1 = kp0 + 32*QS;
        const float* kp2 = kp0 + 64*QS;
        const float* qp  = k_s + (32 + l0)*QS;
        #pragma unroll 2
        for (int d4 = 0; d4 < 32; d4++) {
            ulonglong2 k0 = *(const ulonglong2*)(kp0 + d4*4);
            ulonglong2 k1 = *(const ulonglong2*)(kp1 + d4*4);
            ulonglong2 k2 = *(const ulonglong2*)(kp2 + d4*4);
            #pragma unroll
            for (int i = 0; i < 8; i++) {
                ulonglong2 qv = *(const ulonglong2*)(qp + i*QS + d4*4);
                FMA2(acc2[i][0], qv.x, k0.x); FMA2(acc2[i][0], qv.y, k0.y);
                FMA2(acc2[i][1], qv.x, k1.x); FMA2(acc2[i][1], qv.y, k1.y);
                FMA2(acc2[i][2], qv.x, k2.x); FMA2(acc2[i][2], qv.y, k2.y);
            }
        }
    }
    float acc[8][3];
    #pragma unroll
    for (int i = 0; i < 8; i++)
        #pragma unroll
        for (int mi = 0; mi < 3; mi++)
            acc[i][mi] = lo_f(acc2[i][mi]) + hi_f(acc2[i][mi]);

    // ---------- masks + dup correction + softmax
    const float scale = 0.08838834764831845f;  // 128^-0.5
    {
        int khv[3], kidv[3], ck0[3], ck1[3];
        #pragma unroll
        for (int mi = 0; mi < 3; mi++) {
            int m = kb + mi*32 + lane;
            khv[mi] = s_kh[m]; kidv[mi] = s_kid[m];
            ck0[mi] = s_ck[m*2+0]; ck1[mi] = s_ck[m*2+1];
        }
        #pragma unroll
        for (int i = 0; i < 8; i++) {
            int row = 32 + l0 + i;
            float fq = scale / s_kinv[row];
            int qh = s_kh[row], qid = s_kid[row];
            int cq0 = s_ck[row*2], cq1 = s_ck[row*2+1];
            #pragma unroll
            for (int mi = 0; mi < 3; mi++) {
                float s = acc[i][mi] * fq;
                if (qh != khv[mi])   s -= 1.0e16f;
                if (qid == kidv[mi]) s -= 1.0e8f;
                int d0 = (ck0[mi] - cq0) & (CC-1);
                int d1 = (ck1[mi] - cq1) & (CC-1);
                int dup = ((d0 <= 1) | (d0 == CC-1)) + ((d1 <= 1) | (d1 == CC-1));
                if (dup == 2) s -= 0.6931471805599453f;
                acc[i][mi] = s;
            }
            float mx = fmaxf(acc[i][0], fmaxf(acc[i][1], acc[i][2]));
            #pragma unroll
            for (int o = 16; o; o >>= 1) mx = fmaxf(mx, __shfl_xor_sync(0xffffffffu, mx, o));
            float p0 = expf(acc[i][0]-mx), p1 = expf(acc[i][1]-mx), p2 = expf(acc[i][2]-mx);
            float sum = p0 + p1 + p2;
            #pragma unroll
            for (int o = 16; o; o >>= 1) sum += __shfl_xor_sync(0xffffffffu, sum, o);
            float rinv = 1.0f / sum;
            acc[i][0] = p0*rinv; acc[i][1] = p1*rinv; acc[i][2] = p2*rinv;
            if (lane == 0) g_z[((r*BB + b)*HH + h)*TT + qid] = logf(sum) + mx;
        }
    }
    __syncthreads();

    #pragma unroll
    for (int i = 0; i < 8; i++) {
        float* pr = p_s + (l0 + i)*PS;
        pr[lane]      = acc[i][0];
        pr[32 + lane] = acc[i][1];
        pr[64 + lane] = acc[i][2];
    }
    __syncthreads();

    // ---------- P @ V (outputs packed along d-pairs)
    {
        const int dbase = lane*4;
        u64 o01[8], o23[8];
        #pragma unroll
        for (int i = 0; i < 8; i++) { o01[i]=0ull; o23[i]=0ull; }
        const float* vb = v_s + kb*QS + dbase;
        #pragma unroll 2
        for (int m4 = 0; m4 < 24; m4++) {
            ulonglong2 v0 = *(const ulonglong2*)(vb + (m4*4+0)*QS);
            ulonglong2 v1 = *(const ulonglong2*)(vb + (m4*4+1)*QS);
            ulonglong2 v2 = *(const ulonglong2*)(vb + (m4*4+2)*QS);
            ulonglong2 v3 = *(const ulonglong2*)(vb + (m4*4+3)*QS);
            #pragma unroll
            for (int i = 0; i < 8; i++) {
                float4 pv = *(const float4*)&p_s[(l0+i)*PS + m4*4];
                u64 s0, s1, s2, s3;
                SPLAT2(s0, __float_as_uint(pv.x));
                SPLAT2(s1, __float_as_uint(pv.y));
                SPLAT2(s2, __float_as_uint(pv.z));
                SPLAT2(s3, __float_as_uint(pv.w));
                FMA2(o01[i], s0, v0.x); FMA2(o23[i], s0, v0.y);
                FMA2(o01[i], s1, v1.x); FMA2(o23[i], s1, v1.y);
                FMA2(o01[i], s2, v2.x); FMA2(o23[i], s2, v2.y);
                FMA2(o01[i], s3, v3.x); FMA2(o23[i], s3, v3.y);
            }
        }
        #pragma unroll
        for (int i = 0; i < 8; i++) {
            int qid = s_kid[32 + l0 + i];
            float* op = g_o + ((size_t)((r*BB + b)*HH + h)*TT + qid)*DD + dbase;
            *(float4*)op = make_float4(lo_f(o01[i]), hi_f(o01[i]), lo_f(o23[i]), hi_f(o23[i]));
        }
    }
}

// ==================== round combination ====================
__global__ void __launch_bounds__(256) combine_kernel()
{
    int idx = blockIdx.x*256 + threadIdx.x;
    int d = idx & 127;
    int t = (idx >> 7) & 2047;
    int h = (idx >> 18) & 7;
    int b = idx >> 21;
    int zi = (b*HH + h)*TT + t;
    float z0 = g_z[zi];
    float z1 = g_z[BB*HH*TT + zi];
    float mz = fmaxf(z0, z1);
    float e0 = expf(z0 - mz), e1 = expf(z1 - mz);
    float winv = 1.0f / (e0 + e1);
    int oi = ((b*HH + h)*TT + t)*DD + d;
    float o0 = g_o[oi];
    float o1 = g_o[BB*HH*TT*DD + oi];
    g_ctx[(t*BB + b)*EE + h*DD + d] = (e0*o0 + e1*o1) * winv;
}

// ==================== launch ====================
extern "C" void kernel_launch(void* const* d_in, const int* in_sizes, int n_in,
                              void* d_out, int out_size)
{
    const float* query = (const float*)d_in[0];
    const float* value = (const float*)d_in[2];
    const float* Wq = (const float*)d_in[3];
    const float* bq = (const float*)d_in[4];
    const float* Wv = (const float*)d_in[5];
    const float* bv = (const float*)d_in[6];
    const float* Wo = (const float*)d_in[7];
    const float* bo = (const float*)d_in[8];
    const float* hw = (const float*)d_in[9];

    float* qf;  cudaGetSymbolAddress((void**)&qf,  g_qf);
    float* vf;  cudaGetSymbolAddress((void**)&vf,  g_vf);
    float* ctx; cudaGetSymbolAddress((void**)&ctx, g_ctx);

    cudaFuncSetAttribute(attn_kernel, cudaFuncAttributeMaxDynamicSharedMemorySize, ATTN_SMEM_BYTES);

    dim3 gqv(NTOT/128, (TT*BB)/128, 2);   // fused Wq + Wv projections
    dim3 go (NTOT/128, (TT*BB)/128, 1);   // Wo projection

    sgemm_kernel<<<gqv, 256>>>(query, Wq, bq, qf, value, Wv, bv, vf);
    norm_hash_kernel<<<TT*BB, 128>>>(hw);
    sort_kernel<<<BB*RR*HH, 256>>>();
    attn_kernel<<<BB*RR*HH*16, 512, ATTN_SMEM_BYTES>>>();
    combine_kernel<<<(BB*HH*TT*DD)/256, 256>>>();
    sgemm_kernel<<<go, 256>>>(ctx, Wo, bo, (float*)d_out,
                              ctx, Wo, bo, (float*)d_out);
}

// round 8
// speedup vs baseline: 1.2730x; 1.0105x over previous
#include <cuda_runtime.h>
#include <math.h>
#include <stdint.h>

// Problem constants
#define TT 2048
#define BB 2
#define EE 1024
#define HH 8
#define DD 128
#define RR 2
#define CHUNKC 32
#define CC (TT/CHUNKC)   // 64
#define KTOT 1024
#define NTOT 1024

typedef unsigned long long u64;

// packed f32x2 helpers (sm_100+ PTX; ptxas never auto-fuses these)
#define FMA2(acc, x, y) \
    asm("fma.rn.f32x2 %0, %1, %2, %0;" : "+l"(acc) : "l"(x), "l"(y))
#define SPLAT2(d, s) \
    asm("mov.b64 %0, {%1, %1};" : "=l"(d) : "r"(s))

__device__ __forceinline__ float lo_f(u64 v) { return __uint_as_float((uint32_t)v); }
__device__ __forceinline__ float hi_f(u64 v) { return __uint_as_float((uint32_t)(v >> 32)); }

// -------------------- device scratch --------------------
__device__ float g_qf[TT*BB*EE];
__device__ float g_vf[TT*BB*EE];
__device__ float g_ctx[TT*BB*EE];
__device__ float g_invnorm[TT*BB];
__device__ int   g_hash[BB*RR*HH*TT];
__device__ int   g_perm[BB*RR*HH*TT];
__device__ int   g_inv [BB*RR*HH*TT];
__device__ float g_o[RR*BB*HH*TT*DD];
__device__ float g_z[RR*BB*HH*TT];

// ==================== exact-fp32 SGEMM (f32x2): out = A @ W + bias ====================
// 128x128 CTA tile, 256 threads, 8x8/thread (as 4 m-pairs x 8 n), K-step 16.
#define KS 16
#define NST (KTOT/KS)   // 64

__global__ void __launch_bounds__(256, 2) sgemm_kernel(
    const float* __restrict__ A0, const float* __restrict__ W0,
    const float* __restrict__ b0, float* __restrict__ o0,
    const float* __restrict__ A1, const float* __restrict__ W1,
    const float* __restrict__ b1, float* __restrict__ o1)
{
    const float* A    = blockIdx.z ? A1 : A0;
    const float* W    = blockIdx.z ? W1 : W0;
    const float* bias = blockIdx.z ? b1 : b0;
    float*       out  = blockIdx.z ? o1 : o0;

    __shared__ __align__(16) float As[2][KS][132];
    __shared__ __align__(16) float Bs[2][KS][128];
    __shared__ float bsm[128];

    const int tid = threadIdx.x;
    const int bm = blockIdx.y * 128;
    const int bn = blockIdx.x * 128;
    const int tx = tid & 15;
    const int ty = tid >> 4;

    if (tid < 128) bsm[tid] = bias[bn + tid];

    const int arow = tid >> 2;
    const int akq  = tid & 3;
    const int bkr = tid >> 5;
    const int bn4 = tid & 31;

    const float* Ap0 = A + (size_t)(bm + arow) * KTOT + akq * 4;
    const float* Ap1 = A + (size_t)(bm + 64 + arow) * KTOT + akq * 4;
    const float* Wp0 = W + (size_t)bkr * NTOT + bn + bn4 * 4;
    const float* Wp1 = W + (size_t)(8 + bkr) * NTOT + bn + bn4 * 4;

    float4 pa0, pa1, pb0, pb1;
    u64 acc2[4][8];
    #pragma unroll
    for (int i = 0; i < 4; i++)
        #pragma unroll
        for (int j = 0; j < 8; j++) acc2[i][j] = 0ull;

    pa0 = *(const float4*)(Ap0);
    pa1 = *(const float4*)(Ap1);
    pb0 = *(const float4*)(Wp0);
    pb1 = *(const float4*)(Wp1);
    {
        const int kb = akq * 4;
        As[0][kb+0][arow]    = pa0.x; As[0][kb+1][arow]    = pa0.y;
        As[0][kb+2][arow]    = pa0.z; As[0][kb+3][arow]    = pa0.w;
        As[0][kb+0][64+arow] = pa1.x; As[0][kb+1][64+arow] = pa1.y;
        As[0][kb+2][64+arow] = pa1.z; As[0][kb+3][64+arow] = pa1.w;
        *(float4*)&Bs[0][bkr][bn4*4]   = pb0;
        *(float4*)&Bs[0][8+bkr][bn4*4] = pb1;
    }
    __syncthreads();

    for (int s = 0; s < NST; s++) {
        const int buf = s & 1;
        if (s + 1 < NST) {
            const size_t ko = (size_t)(s + 1) * KS;
            pa0 = *(const float4*)(Ap0 + ko);
            pa1 = *(const float4*)(Ap1 + ko);
            pb0 = *(const float4*)(Wp0 + ko * NTOT);
            pb1 = *(const float4*)(Wp1 + ko * NTOT);
        }
        #pragma unroll
        for (int k = 0; k < KS; k++) {
            ulonglong2 a0 = *(const ulonglong2*)&As[buf][k][ty*4];
            ulonglong2 a1 = *(const ulonglong2*)&As[buf][k][64 + ty*4];
            float4 bv0 = *(const float4*)&Bs[buf][k][tx*4];
            float4 bv1 = *(const float4*)&Bs[buf][k][64 + tx*4];
            u64 ap[4] = {a0.x, a0.y, a1.x, a1.y};
            u64 bs2[8];
            SPLAT2(bs2[0], __float_as_uint(bv0.x));
            SPLAT2(bs2[1], __float_as_uint(bv0.y));
            SPLAT2(bs2[2], __float_as_uint(bv0.z));
            SPLAT2(bs2[3], __float_as_uint(bv0.w));
            SPLAT2(bs2[4], __float_as_uint(bv1.x));
            SPLAT2(bs2[5], __float_as_uint(bv1.y));
            SPLAT2(bs2[6], __float_as_uint(bv1.z));
            SPLAT2(bs2[7], __float_as_uint(bv1.w));
            #pragma unroll
            for (int i = 0; i < 4; i++)
                #pragma unroll
                for (int j = 0; j < 8; j++)
                    FMA2(acc2[i][j], ap[i], bs2[j]);
        }
        if (s + 1 < NST) {
            const int nb = buf ^ 1;
            __syncthreads();
            const int kb = akq * 4;
            As[nb][kb+0][arow]    = pa0.x; As[nb][kb+1][arow]    = pa0.y;
            As[nb][kb+2][arow]    = pa0.z; As[nb][kb+3][arow]    = pa0.w;
            As[nb][kb+0][64+arow] = pa1.x; As[nb][kb+1][64+arow] = pa1.y;
            As[nb][kb+2][64+arow] = pa1.z; As[nb][kb+3][64+arow] = pa1.w;
            *(float4*)&Bs[nb][bkr][bn4*4]   = pb0;
            *(float4*)&Bs[nb][8+bkr][bn4*4] = pb1;
            __syncthreads();
        }
    }

    #pragma unroll
    for (int i2 = 0; i2 < 4; i2++) {
        const int mrow = bm + ((i2 < 2) ? (ty*4 + i2*2) : (64 + ty*4 + (i2-2)*2));
        const int n0 = tx*4, n1 = 64 + tx*4;
        float* r0 = out + (size_t)mrow * NTOT + bn;
        float* r1 = out + (size_t)(mrow+1) * NTOT + bn;
        float4 lo0, lo1, hi0, hi1;
        lo0.x = lo_f(acc2[i2][0]) + bsm[n0+0]; hi0.x = hi_f(acc2[i2][0]) + bsm[n0+0];
        lo0.y = lo_f(acc2[i2][1]) + bsm[n0+1]; hi0.y = hi_f(acc2[i2][1]) + bsm[n0+1];
        lo0.z = lo_f(acc2[i2][2]) + bsm[n0+2]; hi0.z = hi_f(acc2[i2][2]) + bsm[n0+2];
        lo0.w = lo_f(acc2[i2][3]) + bsm[n0+3]; hi0.w = hi_f(acc2[i2][3]) + bsm[n0+3];
        lo1.x = lo_f(acc2[i2][4]) + bsm[n1+0]; hi1.x = hi_f(acc2[i2][4]) + bsm[n1+0];
        lo1.y = lo_f(acc2[i2][5]) + bsm[n1+1]; hi1.y = hi_f(acc2[i2][5]) + bsm[n1+1];
        lo1.z = lo_f(acc2[i2][6]) + bsm[n1+2]; hi1.z = hi_f(acc2[i2][6]) + bsm[n1+2];
        lo1.w = lo_f(acc2[i2][7]) + bsm[n1+3]; hi1.w = hi_f(acc2[i2][7]) + bsm[n1+3];
        *(float4*)(r0 + n0) = lo0;
        *(float4*)(r0 + n1) = lo1;
        *(float4*)(r1 + n0) = hi0;
        *(float4*)(r1 + n1) = hi1;
    }
}

// ==================== norm + hash ====================
__global__ void __launch_bounds__(128) norm_hash_kernel(const float* __restrict__ hw)
{
    int tb = blockIdx.x;
    int t = tb >> 1, b = tb & 1;
    const float* row = g_qf + tb*EE;
    int tid = threadIdx.x, lane = tid & 31, wp = tid >> 5;

    float ss = 0.f;
    for (int i = tid; i < EE; i += 128) { float x = row[i]; ss += x*x; }
    #pragma unroll
    for (int o = 16; o; o >>= 1) ss += __shfl_xor_sync(0xffffffffu, ss, o);
    __shared__ float wred[4];
    if (lane == 0) wred[wp] = ss;
    __syncthreads();
    if (tid == 0) g_invnorm[tb] = 1.0f / sqrtf(wred[0]+wred[1]+wred[2]+wred[3]);

    __shared__ float s_lin[64];
    for (int i = 0; i < 16; i++) {
        int co = wp*16 + i;
        int n = co & 3, h = (co >> 2) & 7, r = co >> 5;
        float s = 0.f;
        const float* x = row + h*DD;
        const float* w = hw + ((r*HH + h)*DD)*4 + n;
        for (int d = lane; d < DD; d += 32) s += x[d] * w[d*4];
        #pragma unroll
        for (int o = 16; o; o >>= 1) s += __shfl_xor_sync(0xffffffffu, s, o);
        if (lane == 0) s_lin[co] = s;
    }
    __syncthreads();
    if (tid < 16) {
        int r = tid >> 3, h = tid & 7;
        const float* L = s_lin + (r*8 + h)*4;
        float best = L[0]; int bi = 0;
        #pragma unroll
        for (int j = 1; j < 8; j++) {
            float v = (j < 4) ? L[j] : -L[j-4];
            if (v > best) { best = v; bi = j; }
        }
        g_hash[((b*RR + r)*HH + h)*TT + t] = bi;
    }
}

// ==================== stable counting sort ====================
__global__ void __launch_bounds__(256) sort_kernel()
{
    int brh = blockIdx.x;
    const int* hs = g_hash + brh*TT;
    int* pp = g_perm + brh*TT;
    int* iv = g_inv  + brh*TT;
    __shared__ int hist[256][8];
    __shared__ int binbase[8];
    int tid = threadIdx.x;
    int base = tid*8;
    int myh[8];
    int loc[8] = {0,0,0,0,0,0,0,0};
    #pragma unroll
    for (int i = 0; i < 8; i++) { int v = hs[base+i]; myh[i] = v; loc[v]++; }
    #pragma unroll
    for (int v = 0; v < 8; v++) hist[tid][v] = loc[v];
    __syncthreads();
    if (tid < 8) {
        int s = 0;
        for (int j = 0; j < 256; j++) { int c = hist[j][tid]; hist[j][tid] = s; s += c; }
        binbase[tid] = s;
    }
    __syncthreads();
    if (tid == 0) {
        int s = 0;
        for (int v = 0; v < 8; v++) { int t0 = binbase[v]; binbase[v] = s; s += t0; }
    }
    __syncthreads();
    int off[8];
    #pragma unroll
    for (int v = 0; v < 8; v++) off[v] = binbase[v] + hist[tid][v];
    #pragma unroll
    for (int i = 0; i < 8; i++) {
        int v = myh[i];
        int pos = off[v]++;
        pp[pos] = base + i;
        iv[base + i] = pos;
    }
}

// ==================== chunked LSH attention (2 chunks / block, V from global) ====================
// Block = (b, r, h, cg) with cg a group of 2 consecutive chunks.
// Window = 4 chunks (128 rows); q rows = window rows 32..95 (q perm == k perm).
// q = k_row * (scale/kinv). V is read directly from global in PV (no v_s).
// P buffer aliases k_s after the QK phase.
#define QS 132
#define PS 100
#define ATTN_SMEM_BYTES (128*QS*4)   // 67584

__global__ void __launch_bounds__(256, 3) attn_kernel()
{
    extern __shared__ float sm[];
    float* k_s = sm;                 // 128 x 132
    float* p_s = sm;                 // aliases k_s after QK: 64 x 100
    __shared__ int s_kid[128], s_kh[128], s_ck[256];
    __shared__ float s_kinv[128];

    int bid = blockIdx.x;
    int cg = bid & 31;
    int h = (bid >> 5) & 7;
    int r = (bid >> 8) & 1;
    int b = bid >> 9;
    int brh = (b*RR + r)*HH + h;
    const int* pp = g_perm + brh*TT;
    int tid = threadIdx.x, lane = tid & 31, wp = tid >> 5;

    if (tid < 128) {
        int wc = (cg*2 + (tid >> 5) + CC - 1) & (CC - 1);
        int kid = pp[wc*32 + (tid & 31)];
        s_kid[tid] = kid;
        s_kh[tid] = g_hash[brh*TT + kid];
        s_kinv[tid] = g_invnorm[kid*BB + b];
        s_ck[tid*2+0] = g_inv[((b*RR+0)*HH+h)*TT + kid] >> 5;
        s_ck[tid*2+1] = g_inv[((b*RR+1)*HH+h)*TT + kid] >> 5;
    }
    __syncthreads();

    // fill normalized k tile: 128 rows x 32 float4
    for (int idx = tid; idx < 128*32; idx += 256) {
        int j = idx >> 5, d4 = idx & 31;
        size_t gbase = (size_t)(s_kid[j]*BB + b)*EE + h*DD + d4*4;
        float4 kq = *(const float4*)&g_qf[gbase];
        float kin = s_kinv[j];
        kq.x *= kin; kq.y *= kin; kq.z *= kin; kq.w *= kin;
        *(float4*)&k_s[j*QS + d4*4] = kq;
    }
    __syncthreads();

    const int kb = (wp >> 2) * 32;   // 0 or 32
    const int l0 = wp * 8;           // q rows: window rows 32+l0 .. 32+l0+7

    // ---------- QK^T (packed along d)
    u64 acc2[8][3];
    #pragma unroll
    for (int i = 0; i < 8; i++) { acc2[i][0]=0ull; acc2[i][1]=0ull; acc2[i][2]=0ull; }
    {
        const float* kp0 = k_s + (kb + lane)*QS;
        const float* kp1 = kp0 + 32*QS;
        const float* kp2 = kp0 + 64*QS;
        const float* qp  = k_s + (32 + l0)*QS;
        #pragma unroll 2
        for (int d4 = 0; d4 < 32; d4++) {
            ulonglong2 k0 = *(const ulonglong2*)(kp0 + d4*4);
            ulonglong2 k1 = *(const ulonglong2*)(kp1 + d4*4);
            ulonglong2 k2 = *(const ulonglong2*)(kp2 + d4*4);
            #pragma unroll
            for (int i = 0; i < 8; i++) {
                ulonglong2 qv = *(const ulonglong2*)(qp + i*QS + d4*4);
                FMA2(acc2[i][0], qv.x, k0.x); FMA2(acc2[i][0], qv.y, k0.y);
                FMA2(acc2[i][1], qv.x, k1.x); FMA2(acc2[i][1], qv.y, k1.y);
                FMA2(acc2[i][2], qv.x, k2.x); FMA2(acc2[i][2], qv.y, k2.y);
            }
        }
    }
    float acc[8][3];
    #pragma unroll
    for (int i = 0; i < 8; i++)
        #pragma unroll
        for (int mi = 0; mi < 3; mi++)
            acc[i][mi] = lo_f(acc2[i][mi]) + hi_f(acc2[i][mi]);

    // ---------- masks + dup correction + softmax
    const float scale = 0.08838834764831845f;  // 128^-0.5
    {
        int khv[3], kidv[3], ck0[3], ck1[3];
        #pragma unroll
        for (int mi = 0; mi < 3; mi++) {
            int m = kb + mi*32 + lane;
            khv[mi] = s_kh[m]; kidv[mi] = s_kid[m];
            ck0[mi] = s_ck[m*2+0]; ck1[mi] = s_ck[m*2+1];
        }
        #pragma unroll
        for (int i = 0; i < 8; i++) {
            int row = 32 + l0 + i;
            float fq = scale / s_kinv[row];
            int qh = s_kh[row], qid = s_kid[row];
            int cq0 = s_ck[row*2], cq1 = s_ck[row*2+1];
            #pragma unroll
            for (int mi = 0; mi < 3; mi++) {
                float s = acc[i][mi] * fq;
                if (qh != khv[mi])   s -= 1.0e16f;
                if (qid == kidv[mi]) s -= 1.0e8f;
                int d0 = (ck0[mi] - cq0) & (CC-1);
                int d1 = (ck1[mi] - cq1) & (CC-1);
                int dup = ((d0 <= 1) | (d0 == CC-1)) + ((d1 <= 1) | (d1 == CC-1));
                if (dup == 2) s -= 0.6931471805599453f;
                acc[i][mi] = s;
            }
            float mx = fmaxf(acc[i][0], fmaxf(acc[i][1], acc[i][2]));
            #pragma unroll
            for (int o = 16; o; o >>= 1) mx = fmaxf(mx, __shfl_xor_sync(0xffffffffu, mx, o));
            float p0 = expf(acc[i][0]-mx), p1 = expf(acc[i][1]-mx), p2 = expf(acc[i][2]-mx);
            float sum = p0 + p1 + p2;
            #pragma unroll
            for (int o = 16; o; o >>= 1) sum += __shfl_xor_sync(0xffffffffu, sum, o);
            float rinv = 1.0f / sum;
            acc[i][0] = p0*rinv; acc[i][1] = p1*rinv; acc[i][2] = p2*rinv;
            if (lane == 0) g_z[((r*BB + b)*HH + h)*TT + qid] = logf(sum) + mx;
        }
    }
    __syncthreads();   // all QK reads of k_s done

    #pragma unroll
    for (int i = 0; i < 8; i++) {
        float* pr = p_s + (l0 + i)*PS;
        pr[lane]      = acc[i][0];
        pr[32 + lane] = acc[i][1];
        pr[64 + lane] = acc[i][2];
    }
    __syncthreads();

    // ---------- P @ V : V read from global (coalesced; L1/L2-resident)
    {
        const int dbase = lane*4;
        const float* vgb = g_vf + (size_t)b*EE + h*DD + dbase;  // + kid*BB*EE per row
        u64 o01[8], o23[8];
        #pragma unroll
        for (int i = 0; i < 8; i++) { o01[i]=0ull; o23[i]=0ull; }
        #pragma unroll 2
        for (int m4 = 0; m4 < 24; m4++) {
            int m0 = kb + m4*4;
            ulonglong2 v0 = *(const ulonglong2*)(vgb + (size_t)s_kid[m0+0]*(BB*EE));
            ulonglong2 v1 = *(const ulonglong2*)(vgb + (size_t)s_kid[m0+1]*(BB*EE));
            ulonglong2 v2 = *(const ulonglong2*)(vgb + (size_t)s_kid[m0+2]*(BB*EE));
            ulonglong2 v3 = *(const ulonglong2*)(vgb + (size_t)s_kid[m0+3]*(BB*EE));
            #pragma unroll
            for (int i = 0; i < 8; i++) {
                float4 pv = *(const float4*)&p_s[(l0+i)*PS + m4*4];
                u64 s0, s1, s2, s3;
                SPLAT2(s0, __float_as_uint(pv.x));
                SPLAT2(s1, __float_as_uint(pv.y));
                SPLAT2(s2, __float_as_uint(pv.z));
                SPLAT2(s3, __float_as_uint(pv.w));
                FMA2(o01[i], s0, v0.x); FMA2(o23[i], s0, v0.y);
                FMA2(o01[i], s1, v1.x); FMA2(o23[i], s1, v1.y);
                FMA2(o01[i], s2, v2.x); FMA2(o23[i], s2, v2.y);
                FMA2(o01[i], s3, v3.x); FMA2(o23[i], s3, v3.y);
            }
        }
        #pragma unroll
        for (int i = 0; i < 8; i++) {
            int qid = s_kid[32 + l0 + i];
            float* op = g_o + ((size_t)((r*BB + b)*HH + h)*TT + qid)*DD + dbase;
            *(float4*)op = make_float4(lo_f(o01[i]), hi_f(o01[i]), lo_f(o23[i]), hi_f(o23[i]));
        }
    }
}

// ==================== round combination ====================
__global__ void __launch_bounds__(256) combine_kernel()
{
    int idx = blockIdx.x*256 + threadIdx.x;
    int d = idx & 127;
    int t = (idx >> 7) & 2047;
    int h = (idx >> 18) & 7;
    int b = idx >> 21;
    int zi = (b*HH + h)*TT + t;
    float z0 = g_z[zi];
    float z1 = g_z[BB*HH*TT + zi];
    float mz = fmaxf(z0, z1);
    float e0 = expf(z0 - mz), e1 = expf(z1 - mz);
    float winv = 1.0f / (e0 + e1);
    int oi = ((b*HH + h)*TT + t)*DD + d;
    float o0 = g_o[oi];
    float o1 = g_o[BB*HH*TT*DD + oi];
    g_ctx[(t*BB + b)*EE + h*DD + d] = (e0*o0 + e1*o1) * winv;
}

// ==================== launch ====================
extern "C" void kernel_launch(void* const* d_in, const int* in_sizes, int n_in,
                              void* d_out, int out_size)
{
    const float* query = (const float*)d_in[0];
    const float* value = (const float*)d_in[2];
    const float* Wq = (const float*)d_in[3];
    const float* bq = (const float*)d_in[4];
    const float* Wv = (const float*)d_in[5];
    const float* bv = (const float*)d_in[6];
    const float* Wo = (const float*)d_in[7];
    const float* bo = (const float*)d_in[8];
    const float* hw = (const float*)d_in[9];

    float* qf;  cudaGetSymbolAddress((void**)&qf,  g_qf);
    float* vf;  cudaGetSymbolAddress((void**)&vf,  g_vf);
    float* ctx; cudaGetSymbolAddress((void**)&ctx, g_ctx);

    cudaFuncSetAttribute(attn_kernel, cudaFuncAttributeMaxDynamicSharedMemorySize, ATTN_SMEM_BYTES);

    dim3 gqv(NTOT/128, (TT*BB)/128, 2);   // fused Wq + Wv projections
    dim3 go (NTOT/128, (TT*BB)/128, 1);   // Wo projection

    sgemm_kernel<<<gqv, 256>>>(query, Wq, bq, qf, value, Wv, bv, vf);
    norm_hash_kernel<<<TT*BB, 128>>>(hw);
    sort_kernel<<<BB*RR*HH, 256>>>();
    attn_kernel<<<BB*RR*HH*32, 256, ATTN_SMEM_BYTES>>>();
    combine_kernel<<<(BB*HH*TT*DD)/256, 256>>>();
    sgemm_kernel<<<go, 256>>>(ctx, Wo, bo, (float*)d_out,
                              ctx, Wo, bo, (float*)d_out);
}

// round 9
// speedup vs baseline: 1.3202x; 1.0371x over previous
#include <cuda_runtime.h>
#include <math.h>
#include <stdint.h>

// Problem constants
#define TT 2048
#define BB 2
#define EE 1024
#define HH 8
#define DD 128
#define RR 2
#define CHUNKC 32
#define CC (TT/CHUNKC)   // 64
#define KTOT 1024
#define NTOT 1024

typedef unsigned long long u64;

// packed f32x2 helpers (sm_100+ PTX; ptxas never auto-fuses these)
#define FMA2(acc, x, y) \
    asm("fma.rn.f32x2 %0, %1, %2, %0;" : "+l"(acc) : "l"(x), "l"(y))
#define SPLAT2(d, s) \
    asm("mov.b64 %0, {%1, %1};" : "=l"(d) : "r"(s))

__device__ __forceinline__ float lo_f(u64 v) { return __uint_as_float((uint32_t)v); }
__device__ __forceinline__ float hi_f(u64 v) { return __uint_as_float((uint32_t)(v >> 32)); }

__device__ __forceinline__ uint32_t smem_u32(const void* p) {
    uint32_t a;
    asm("{ .reg .u64 t; cvta.to.shared.u64 t, %1; cvt.u32.u64 %0, t; }" : "=r"(a) : "l"(p));
    return a;
}
__device__ __forceinline__ void cp_async16(uint32_t smem_addr, const void* gptr) {
    asm volatile("cp.async.ca.shared.global [%0], [%1], 16;" :: "r"(smem_addr), "l"(gptr));
}
#define CP_COMMIT() asm volatile("cp.async.commit_group;" ::: "memory")
#define CP_WAIT0()  asm volatile("cp.async.wait_group 0;" ::: "memory")

// -------------------- device scratch --------------------
__device__ float g_qf[TT*BB*EE];
__device__ float g_vf[TT*BB*EE];
__device__ float g_ctx[TT*BB*EE];
__device__ float g_invnorm[TT*BB];
__device__ int   g_hash[BB*RR*HH*TT];
__device__ int   g_perm[BB*RR*HH*TT];
__device__ int   g_inv [BB*RR*HH*TT];
__device__ float g_o[RR*BB*HH*TT*DD];
__device__ float g_z[RR*BB*HH*TT];

// ==================== exact-fp32 SGEMM (f32x2 + cp.async B): out = A @ W + bias ====================
// 128x128 CTA tile, 256 threads, 8x8/thread (4 m-pairs x 8 n), K-step 16, double-buffered.
#define KS 16
#define NST (KTOT/KS)   // 64

__global__ void __launch_bounds__(256, 2) sgemm_kernel(
    const float* __restrict__ A0, const float* __restrict__ W0,
    const float* __restrict__ b0, float* __restrict__ o0,
    const float* __restrict__ A1, const float* __restrict__ W1,
    const float* __restrict__ b1, float* __restrict__ o1)
{
    const float* A    = blockIdx.z ? A1 : A0;
    const float* W    = blockIdx.z ? W1 : W0;
    const float* bias = blockIdx.z ? b1 : b0;
    float*       out  = blockIdx.z ? o1 : o0;

    __shared__ __align__(16) float As[2][KS][132];
    __shared__ __align__(16) float Bs[2][KS][128];
    __shared__ float bsm[128];

    const int tid = threadIdx.x;
    const int bm = blockIdx.y * 128;
    const int bn = blockIdx.x * 128;
    const int tx = tid & 15;
    const int ty = tid >> 4;

    if (tid < 128) bsm[tid] = bias[bn + tid];

    const int arow = tid >> 2;
    const int akq  = tid & 3;
    const int bkr = tid >> 5;
    const int bn4 = tid & 31;

    const float* Ap0 = A + (size_t)(bm + arow) * KTOT + akq * 4;
    const float* Ap1 = A + (size_t)(bm + 64 + arow) * KTOT + akq * 4;
    const float* Wp0 = W + (size_t)bkr * NTOT + bn + bn4 * 4;
    const float* Wp1 = W + (size_t)(8 + bkr) * NTOT + bn + bn4 * 4;

    const uint32_t bs_a0 = smem_u32(&Bs[0][bkr][bn4*4]);
    const uint32_t bs_a1 = smem_u32(&Bs[0][8+bkr][bn4*4]);
    const uint32_t bs_b0 = smem_u32(&Bs[1][bkr][bn4*4]);
    const uint32_t bs_b1 = smem_u32(&Bs[1][8+bkr][bn4*4]);

    float4 pa0, pa1;
    u64 acc2[4][8];
    #pragma unroll
    for (int i = 0; i < 4; i++)
        #pragma unroll
        for (int j = 0; j < 8; j++) acc2[i][j] = 0ull;

    // stage 0
    pa0 = *(const float4*)(Ap0);
    pa1 = *(const float4*)(Ap1);
    cp_async16(bs_a0, Wp0);
    cp_async16(bs_a1, Wp1);
    CP_COMMIT();
    {
        const int kb = akq * 4;
        As[0][kb+0][arow]    = pa0.x; As[0][kb+1][arow]    = pa0.y;
        As[0][kb+2][arow]    = pa0.z; As[0][kb+3][arow]    = pa0.w;
        As[0][kb+0][64+arow] = pa1.x; As[0][kb+1][64+arow] = pa1.y;
        As[0][kb+2][64+arow] = pa1.z; As[0][kb+3][64+arow] = pa1.w;
    }
    CP_WAIT0();
    __syncthreads();

    for (int s = 0; s < NST; s++) {
        const int buf = s & 1;
        if (s + 1 < NST) {
            const size_t ko = (size_t)(s + 1) * KS;
            pa0 = *(const float4*)(Ap0 + ko);
            pa1 = *(const float4*)(Ap1 + ko);
            // Bs[nb] free: compute(s-1) finished reading it before the last sync
            cp_async16(buf ? bs_a0 : bs_b0, Wp0 + ko * NTOT);
            cp_async16(buf ? bs_a1 : bs_b1, Wp1 + ko * NTOT);
            CP_COMMIT();
        }
        #pragma unroll
        for (int k = 0; k < KS; k++) {
            ulonglong2 a0 = *(const ulonglong2*)&As[buf][k][ty*4];
            ulonglong2 a1 = *(const ulonglong2*)&As[buf][k][64 + ty*4];
            float4 bv0 = *(const float4*)&Bs[buf][k][tx*4];
            float4 bv1 = *(const float4*)&Bs[buf][k][64 + tx*4];
            u64 ap[4] = {a0.x, a0.y, a1.x, a1.y};
            u64 bs2[8];
            SPLAT2(bs2[0], __float_as_uint(bv0.x));
            SPLAT2(bs2[1], __float_as_uint(bv0.y));
            SPLAT2(bs2[2], __float_as_uint(bv0.z));
            SPLAT2(bs2[3], __float_as_uint(bv0.w));
            SPLAT2(bs2[4], __float_as_uint(bv1.x));
            SPLAT2(bs2[5], __float_as_uint(bv1.y));
            SPLAT2(bs2[6], __float_as_uint(bv1.z));
            SPLAT2(bs2[7], __float_as_uint(bv1.w));
            #pragma unroll
            for (int i = 0; i < 4; i++)
                #pragma unroll
                for (int j = 0; j < 8; j++)
                    FMA2(acc2[i][j], ap[i], bs2[j]);
        }
        if (s + 1 < NST) {
            const int nb = buf ^ 1;
            __syncthreads();
            const int kb = akq * 4;
            As[nb][kb+0][arow]    = pa0.x; As[nb][kb+1][arow]    = pa0.y;
            As[nb][kb+2][arow]    = pa0.z; As[nb][kb+3][arow]    = pa0.w;
            As[nb][kb+0][64+arow] = pa1.x; As[nb][kb+1][64+arow] = pa1.y;
            As[nb][kb+2][64+arow] = pa1.z; As[nb][kb+3][64+arow] = pa1.w;
            CP_WAIT0();
            __syncthreads();
        }
    }

    #pragma unroll
    for (int i2 = 0; i2 < 4; i2++) {
        const int mrow = bm + ((i2 < 2) ? (ty*4 + i2*2) : (64 + ty*4 + (i2-2)*2));
        const int n0 = tx*4, n1 = 64 + tx*4;
        float* r0 = out + (size_t)mrow * NTOT + bn;
        float* r1 = out + (size_t)(mrow+1) * NTOT + bn;
        float4 lo0, lo1, hi0, hi1;
        lo0.x = lo_f(acc2[i2][0]) + bsm[n0+0]; hi0.x = hi_f(acc2[i2][0]) + bsm[n0+0];
        lo0.y = lo_f(acc2[i2][1]) + bsm[n0+1]; hi0.y = hi_f(acc2[i2][1]) + bsm[n0+1];
        lo0.z = lo_f(acc2[i2][2]) + bsm[n0+2]; hi0.z = hi_f(acc2[i2][2]) + bsm[n0+2];
        lo0.w = lo_f(acc2[i2][3]) + bsm[n0+3]; hi0.w = hi_f(acc2[i2][3]) + bsm[n0+3];
        lo1.x = lo_f(acc2[i2][4]) + bsm[n1+0]; hi1.x = hi_f(acc2[i2][4]) + bsm[n1+0];
        lo1.y = lo_f(acc2[i2][5]) + bsm[n1+1]; hi1.y = hi_f(acc2[i2][5]) + bsm[n1+1];
        lo1.z = lo_f(acc2[i2][6]) + bsm[n1+2]; hi1.z = hi_f(acc2[i2][6]) + bsm[n1+2];
        lo1.w = lo_f(acc2[i2][7]) + bsm[n1+3]; hi1.w = hi_f(acc2[i2][7]) + bsm[n1+3];
        *(float4*)(r0 + n0) = lo0;
        *(float4*)(r0 + n1) = lo1;
        *(float4*)(r1 + n0) = hi0;
        *(float4*)(r1 + n1) = hi1;
    }
}

// ==================== norm + hash ====================
__global__ void __launch_bounds__(128) norm_hash_kernel(const float* __restrict__ hw)
{
    int tb = blockIdx.x;
    int t = tb >> 1, b = tb & 1;
    const float* row = g_qf + tb*EE;
    int tid = threadIdx.x, lane = tid & 31, wp = tid >> 5;

    float ss = 0.f;
    for (int i = tid; i < EE; i += 128) { float x = row[i]; ss += x*x; }
    #pragma unroll
    for (int o = 16; o; o >>= 1) ss += __shfl_xor_sync(0xffffffffu, ss, o);
    __shared__ float wred[4];
    if (lane == 0) wred[wp] = ss;
    __syncthreads();
    if (tid == 0) g_invnorm[tb] = 1.0f / sqrtf(wred[0]+wred[1]+wred[2]+wred[3]);

    __shared__ float s_lin[64];
    for (int i = 0; i < 16; i++) {
        int co = wp*16 + i;
        int n = co & 3, h = (co >> 2) & 7, r = co >> 5;
        float s = 0.f;
        const float* x = row + h*DD;
        const float* w = hw + ((r*HH + h)*DD)*4 + n;
        for (int d = lane; d < DD; d += 32) s += x[d] * w[d*4];
        #pragma unroll
        for (int o = 16; o; o >>= 1) s += __shfl_xor_sync(0xffffffffu, s, o);
        if (lane == 0) s_lin[co] = s;
    }
    __syncthreads();
    if (tid < 16) {
        int r = tid >> 3, h = tid & 7;
        const float* L = s_lin + (r*8 + h)*4;
        float best = L[0]; int bi = 0;
        #pragma unroll
        for (int j = 1; j < 8; j++) {
            float v = (j < 4) ? L[j] : -L[j-4];
            if (v > best) { best = v; bi = j; }
        }
        g_hash[((b*RR + r)*HH + h)*TT + t] = bi;
    }
}

// ==================== stable counting sort ====================
__global__ void __launch_bounds__(256) sort_kernel()
{
    int brh = blockIdx.x;
    const int* hs = g_hash + brh*TT;
    int* pp = g_perm + brh*TT;
    int* iv = g_inv  + brh*TT;
    __shared__ int hist[256][8];
    __shared__ int binbase[8];
    int tid = threadIdx.x;
    int base = tid*8;
    int myh[8];
    int loc[8] = {0,0,0,0,0,0,0,0};
    #pragma unroll
    for (int i = 0; i < 8; i++) { int v = hs[base+i]; myh[i] = v; loc[v]++; }
    #pragma unroll
    for (int v = 0; v < 8; v++) hist[tid][v] = loc[v];
    __syncthreads();
    if (tid < 8) {
        int s = 0;
        for (int j = 0; j < 256; j++) { int c = hist[j][tid]; hist[j][tid] = s; s += c; }
        binbase[tid] = s;
    }
    __syncthreads();
    if (tid == 0) {
        int s = 0;
        for (int v = 0; v < 8; v++) { int t0 = binbase[v]; binbase[v] = s; s += t0; }
    }
    __syncthreads();
    int off[8];
    #pragma unroll
    for (int v = 0; v < 8; v++) off[v] = binbase[v] + hist[tid][v];
    #pragma unroll
    for (int i = 0; i < 8; i++) {
        int v = myh[i];
        int pos = off[v]++;
        pp[pos] = base + i;
        iv[base + i] = pos;
    }
}

// ==================== chunked LSH attention (2 chunks / block, V from global) ====================
#define QS 132
#define PS 100
#define ATTN_SMEM_BYTES (128*QS*4)   // 67584

__global__ void __launch_bounds__(256, 3) attn_kernel()
{
    extern __shared__ float sm[];
    float* k_s = sm;                 // 128 x 132
    float* p_s = sm;                 // aliases k_s after QK: 64 x 100
    __shared__ int s_kid[128], s_kh[128], s_ck[256];
    __shared__ float s_kinv[128];
    __shared__ u64 s_vp[128];        // precomputed V row pointers

    int bid = blockIdx.x;
    int cg = bid & 31;
    int h = (bid >> 5) & 7;
    int r = (bid >> 8) & 1;
    int b = bid >> 9;
    int brh = (b*RR + r)*HH + h;
    const int* pp = g_perm + brh*TT;
    int tid = threadIdx.x, lane = tid & 31, wp = tid >> 5;

    if (tid < 128) {
        int wc = (cg*2 + (tid >> 5) + CC - 1) & (CC - 1);
        int kid = pp[wc*32 + (tid & 31)];
        s_kid[tid] = kid;
        s_kh[tid] = g_hash[brh*TT + kid];
        s_kinv[tid] = g_invnorm[kid*BB + b];
        s_ck[tid*2+0] = g_inv[((b*RR+0)*HH+h)*TT + kid] >> 5;
        s_ck[tid*2+1] = g_inv[((b*RR+1)*HH+h)*TT + kid] >> 5;
        s_vp[tid] = (u64)(g_vf + (size_t)kid*(BB*EE) + (size_t)b*EE + h*DD);
    }
    __syncthreads();

    // fill normalized k tile: 128 rows x 32 float4
    for (int idx = tid; idx < 128*32; idx += 256) {
        int j = idx >> 5, d4 = idx & 31;
        size_t gbase = (size_t)(s_kid[j]*BB + b)*EE + h*DD + d4*4;
        float4 kq = *(const float4*)&g_qf[gbase];
        float kin = s_kinv[j];
        kq.x *= kin; kq.y *= kin; kq.z *= kin; kq.w *= kin;
        *(float4*)&k_s[j*QS + d4*4] = kq;
    }
    __syncthreads();

    const int kb = (wp >> 2) * 32;   // 0 or 32
    const int l0 = wp * 8;           // q rows: window rows 32+l0 .. 32+l0+7

    // ---------- QK^T (packed along d)
    u64 acc2[8][3];
    #pragma unroll
    for (int i = 0; i < 8; i++) { acc2[i][0]=0ull; acc2[i][1]=0ull; acc2[i][2]=0ull; }
    {
        const float* kp0 = k_s + (kb + lane)*QS;
        const float* kp1 = kp0 + 32*QS;
        const float* kp2 = kp0 + 64*QS;
        const float* qp  = k_s + (32 + l0)*QS;
        #pragma unroll 2
        for (int d4 = 0; d4 < 32; d4++) {
            ulonglong2 k0 = *(const ulonglong2*)(kp0 + d4*4);
            ulonglong2 k1 = *(const ulonglong2*)(kp1 + d4*4);
            ulonglong2 k2 = *(const ulonglong2*)(kp2 + d4*4);
            #pragma unroll
            for (int i = 0; i < 8; i++) {
                ulonglong2 qv = *(const ulonglong2*)(qp + i*QS + d4*4);
                FMA2(acc2[i][0], qv.x, k0.x); FMA2(acc2[i][0], qv.y, k0.y);
                FMA2(acc2[i][1], qv.x, k1.x); FMA2(acc2[i][1], qv.y, k1.y);
                FMA2(acc2[i][2], qv.x, k2.x); FMA2(acc2[i][2], qv.y, k2.y);
            }
        }
    }
    float acc[8][3];
    #pragma unroll
    for (int i = 0; i < 8; i++)
        #pragma unroll
        for (int mi = 0; mi < 3; mi++)
            acc[i][mi] = lo_f(acc2[i][mi]) + hi_f(acc2[i][mi]);

    // ---------- masks + dup correction + softmax
    const float scale = 0.08838834764831845f;  // 128^-0.5
    {
        int khv[3], kidv[3], ck0[3], ck1[3];
        #pragma unroll
        for (int mi = 0; mi < 3; mi++) {
            int m = kb + mi*32 + lane;
            khv[mi] = s_kh[m]; kidv[mi] = s_kid[m];
            ck0[mi] = s_ck[m*2+0]; ck1[mi] = s_ck[m*2+1];
        }
        #pragma unroll
        for (int i = 0; i < 8; i++) {
            int row = 32 + l0 + i;
            float fq = scale / s_kinv[row];
            int qh = s_kh[row], qid = s_kid[row];
            int cq0 = s_ck[row*2], cq1 = s_ck[row*2+1];
            #pragma unroll
            for (int mi = 0; mi < 3; mi++) {
                float s = acc[i][mi] * fq;
                if (qh != khv[mi])   s -= 1.0e16f;
                if (qid == kidv[mi]) s -= 1.0e8f;
                int d0 = (ck0[mi] - cq0) & (CC-1);
                int d1 = (ck1[mi] - cq1) & (CC-1);
                int dup = ((d0 <= 1) | (d0 == CC-1)) + ((d1 <= 1) | (d1 == CC-1));
                if (dup == 2) s -= 0.6931471805599453f;
                acc[i][mi] = s;
            }
            float mx = fmaxf(acc[i][0], fmaxf(acc[i][1], acc[i][2]));
            #pragma unroll
            for (int o = 16; o; o >>= 1) mx = fmaxf(mx, __shfl_xor_sync(0xffffffffu, mx, o));
            float p0 = __expf(acc[i][0]-mx), p1 = __expf(acc[i][1]-mx), p2 = __expf(acc[i][2]-mx);
            float sum = p0 + p1 + p2;
            #pragma unroll
            for (int o = 16; o; o >>= 1) sum += __shfl_xor_sync(0xffffffffu, sum, o);
            float rinv = 1.0f / sum;
            acc[i][0] = p0*rinv; acc[i][1] = p1*rinv; acc[i][2] = p2*rinv;
            if (lane == 0) g_z[((r*BB + b)*HH + h)*TT + qid] = __logf(sum) + mx;
        }
    }
    __syncthreads();   // all QK reads of k_s done

    #pragma unroll
    for (int i = 0; i < 8; i++) {
        float* pr = p_s + (l0 + i)*PS;
        pr[lane]      = acc[i][0];
        pr[32 + lane] = acc[i][1];
        pr[64 + lane] = acc[i][2];
    }
    __syncthreads();

    // ---------- P @ V : V via precomputed row pointers (L1/L2-resident)
    {
        const int dbase = lane*4;
        u64 o01[8], o23[8];
        #pragma unroll
        for (int i = 0; i < 8; i++) { o01[i]=0ull; o23[i]=0ull; }
        #pragma unroll 2
        for (int m4 = 0; m4 < 24; m4++) {
            int m0 = kb + m4*4;
            ulonglong2 v0 = *(const ulonglong2*)((const float*)s_vp[m0+0] + dbase);
            ulonglong2 v1 = *(const ulonglong2*)((const float*)s_vp[m0+1] + dbase);
            ulonglong2 v2 = *(const ulonglong2*)((const float*)s_vp[m0+2] + dbase);
            ulonglong2 v3 = *(const ulonglong2*)((const float*)s_vp[m0+3] + dbase);
            #pragma unroll
            for (int i = 0; i < 8; i++) {
                float4 pv = *(const float4*)&p_s[(l0+i)*PS + m4*4];
                u64 s0, s1, s2, s3;
                SPLAT2(s0, __float_as_uint(pv.x));
                SPLAT2(s1, __float_as_uint(pv.y));
                SPLAT2(s2, __float_as_uint(pv.z));
                SPLAT2(s3, __float_as_uint(pv.w));
                FMA2(o01[i], s0, v0.x); FMA2(o23[i], s0, v0.y);
                FMA2(o01[i], s1, v1.x); FMA2(o23[i], s1, v1.y);
                FMA2(o01[i], s2, v2.x); FMA2(o23[i], s2, v2.y);
                FMA2(o01[i], s3, v3.x); FMA2(o23[i], s3, v3.y);
            }
        }
        #pragma unroll
        for (int i = 0; i < 8; i++) {
            int qid = s_kid[32 + l0 + i];
            float* op = g_o + ((size_t)((r*BB + b)*HH + h)*TT + qid)*DD + dbase;
            *(float4*)op = make_float4(lo_f(o01[i]), hi_f(o01[i]), lo_f(o23[i]), hi_f(o23[i]));
        }
    }
}

// ==================== round combination ====================
__global__ void __launch_bounds__(256) combine_kernel()
{
    int idx = blockIdx.x*256 + threadIdx.x;
    int d = idx & 127;
    int t = (idx >> 7) & 2047;
    int h = (idx >> 18) & 7;
    int b = idx >> 21;
    int zi = (b*HH + h)*TT + t;
    float z0 = g_z[zi];
    float z1 = g_z[BB*HH*TT + zi];
    float mz = fmaxf(z0, z1);
    float e0 = __expf(z0 - mz), e1 = __expf(z1 - mz);
    float winv = 1.0f / (e0 + e1);
    int oi = ((b*HH + h)*TT + t)*DD + d;
    float o0 = g_o[oi];
    float o1 = g_o[BB*HH*TT*DD + oi];
    g_ctx[(t*BB + b)*EE + h*DD + d] = (e0*o0 + e1*o1) * winv;
}

// ==================== launch ====================
extern "C" void kernel_launch(void* const* d_in, const int* in_sizes, int n_in,
                              void* d_out, int out_size)
{
    const float* query = (const float*)d_in[0];
    const float* value = (const float*)d_in[2];
    const float* Wq = (const float*)d_in[3];
    const float* bq = (const float*)d_in[4];
    const float* Wv = (const float*)d_in[5];
    const float* bv = (const float*)d_in[6];
    const float* Wo = (const float*)d_in[7];
    const float* bo = (const float*)d_in[8];
    const float* hw = (const float*)d_in[9];

    float* qf;  cudaGetSymbolAddress((void**)&qf,  g_qf);
    float* vf;  cudaGetSymbolAddress((void**)&vf,  g_vf);
    float* ctx; cudaGetSymbolAddress((void**)&ctx, g_ctx);

    cudaFuncSetAttribute(attn_kernel, cudaFuncAttributeMaxDynamicSharedMemorySize, ATTN_SMEM_BYTES);

    dim3 gqv(NTOT/128, (TT*BB)/128, 2);   // fused Wq + Wv projections
    dim3 go (NTOT/128, (TT*BB)/128, 1);   // Wo projection

    sgemm_kernel<<<gqv, 256>>>(query, Wq, bq, qf, value, Wv, bv, vf);
    norm_hash_kernel<<<TT*BB, 128>>>(hw);
    sort_kernel<<<BB*RR*HH, 256>>>();
    attn_kernel<<<BB*RR*HH*32, 256, ATTN_SMEM_BYTES>>>();
    combine_kernel<<<(BB*HH*TT*DD)/256, 256>>>();
    sgemm_kernel<<<go, 256>>>(ctx, Wo, bo, (float*)d_out,
                              ctx, Wo, bo, (float*)d_out);
}

// round 11
// speedup vs baseline: 1.3330x; 1.0098x over previous
#include <cuda_runtime.h>
#include <math.h>
#include <stdint.h>

// Problem constants
#define TT 2048
#define BB 2
#define EE 1024
#define HH 8
#define DD 128
#define RR 2
#define CHUNKC 32
#define CC (TT/CHUNKC)   // 64
#define KTOT 1024
#define NTOT 1024

typedef unsigned long long u64;

// packed f32x2 helpers (sm_100+ PTX; ptxas never auto-fuses these)
#define FMA2(acc, x, y) \
    asm("fma.rn.f32x2 %0, %1, %2, %0;" : "+l"(acc) : "l"(x), "l"(y))
#define SPLAT2(d, s) \
    asm("mov.b64 %0, {%1, %1};" : "=l"(d) : "r"(s))

__device__ __forceinline__ float lo_f(u64 v) { return __uint_as_float((uint32_t)v); }
__device__ __forceinline__ float hi_f(u64 v) { return __uint_as_float((uint32_t)(v >> 32)); }

__device__ __forceinline__ uint32_t smem_u32(const void* p) {
    uint32_t a;
    asm("{ .reg .u64 t; cvta.to.shared.u64 t, %1; cvt.u32.u64 %0, t; }" : "=r"(a) : "l"(p));
    return a;
}
__device__ __forceinline__ void cp_async16(uint32_t smem_addr, const void* gptr) {
    asm volatile("cp.async.ca.shared.global [%0], [%1], 16;" :: "r"(smem_addr), "l"(gptr));
}
#define CP_COMMIT() asm volatile("cp.async.commit_group;" ::: "memory")
#define CP_WAIT0()  asm volatile("cp.async.wait_group 0;" ::: "memory")

// -------------------- device scratch --------------------
__device__ float g_qf[TT*BB*EE];
__device__ float g_vf[TT*BB*EE];
__device__ float g_ctx[TT*BB*EE];
__device__ float g_invnorm[TT*BB];
__device__ int   g_hash[BB*RR*HH*TT];
__device__ int   g_perm[BB*RR*HH*TT];
__device__ int   g_inv [BB*RR*HH*TT];
__device__ float g_o[RR*BB*HH*TT*DD];
__device__ float g_z[RR*BB*HH*TT];

// ==================== exact-fp32 SGEMM (f32x2 + cp.async B): out = A @ W + bias ====================
#define KS 16
#define NST (KTOT/KS)   // 64

__global__ void __launch_bounds__(256, 2) sgemm_kernel(
    const float* __restrict__ A0, const float* __restrict__ W0,
    const float* __restrict__ b0, float* __restrict__ o0,
    const float* __restrict__ A1, const float* __restrict__ W1,
    const float* __restrict__ b1, float* __restrict__ o1)
{
    const float* A    = blockIdx.z ? A1 : A0;
    const float* W    = blockIdx.z ? W1 : W0;
    const float* bias = blockIdx.z ? b1 : b0;
    float*       out  = blockIdx.z ? o1 : o0;

    __shared__ __align__(16) float As[2][KS][132];
    __shared__ __align__(16) float Bs[2][KS][128];
    __shared__ float bsm[128];

    const int tid = threadIdx.x;
    const int bm = blockIdx.y * 128;
    const int bn = blockIdx.x * 128;
    const int tx = tid & 15;
    const int ty = tid >> 4;

    if (tid < 128) bsm[tid] = bias[bn + tid];

    const int arow = tid >> 2;
    const int akq  = tid & 3;
    const int bkr = tid >> 5;
    const int bn4 = tid & 31;

    const float* Ap0 = A + (size_t)(bm + arow) * KTOT + akq * 4;
    const float* Ap1 = A + (size_t)(bm + 64 + arow) * KTOT + akq * 4;
    const float* Wp0 = W + (size_t)bkr * NTOT + bn + bn4 * 4;
    const float* Wp1 = W + (size_t)(8 + bkr) * NTOT + bn + bn4 * 4;

    const uint32_t bs_a0 = smem_u32(&Bs[0][bkr][bn4*4]);
    const uint32_t bs_a1 = smem_u32(&Bs[0][8+bkr][bn4*4]);
    const uint32_t bs_b0 = smem_u32(&Bs[1][bkr][bn4*4]);
    const uint32_t bs_b1 = smem_u32(&Bs[1][8+bkr][bn4*4]);

    float4 pa0, pa1;
    u64 acc2[4][8];
    #pragma unroll
    for (int i = 0; i < 4; i++)
        #pragma unroll
        for (int j = 0; j < 8; j++) acc2[i][j] = 0ull;

    pa0 = *(const float4*)(Ap0);
    pa1 = *(const float4*)(Ap1);
    cp_async16(bs_a0, Wp0);
    cp_async16(bs_a1, Wp1);
    CP_COMMIT();
    {
        const int kb = akq * 4;
        As[0][kb+0][arow]    = pa0.x; As[0][kb+1][arow]    = pa0.y;
        As[0][kb+2][arow]    = pa0.z; As[0][kb+3][arow]    = pa0.w;
        As[0][kb+0][64+arow] = pa1.x; As[0][kb+1][64+arow] = pa1.y;
        As[0][kb+2][64+arow] = pa1.z; As[0][kb+3][64+arow] = pa1.w;
    }
    CP_WAIT0();
    __syncthreads();

    for (int s = 0; s < NST; s++) {
        const int buf = s & 1;
        if (s + 1 < NST) {
            const size_t ko = (size_t)(s + 1) * KS;
            pa0 = *(const float4*)(Ap0 + ko);
            pa1 = *(const float4*)(Ap1 + ko);
            cp_async16(buf ? bs_a0 : bs_b0, Wp0 + ko * NTOT);
            cp_async16(buf ? bs_a1 : bs_b1, Wp1 + ko * NTOT);
            CP_COMMIT();
        }
        #pragma unroll
        for (int k = 0; k < KS; k++) {
            ulonglong2 a0 = *(const ulonglong2*)&As[buf][k][ty*4];
            ulonglong2 a1 = *(const ulonglong2*)&As[buf][k][64 + ty*4];
            float4 bv0 = *(const float4*)&Bs[buf][k][tx*4];
            float4 bv1 = *(const float4*)&Bs[buf][k][64 + tx*4];
            u64 ap[4] = {a0.x, a0.y, a1.x, a1.y};
            u64 bs2[8];
            SPLAT2(bs2[0], __float_as_uint(bv0.x));
            SPLAT2(bs2[1], __float_as_uint(bv0.y));
            SPLAT2(bs2[2], __float_as_uint(bv0.z));
            SPLAT2(bs2[3], __float_as_uint(bv0.w));
            SPLAT2(bs2[4], __float_as_uint(bv1.x));
            SPLAT2(bs2[5], __float_as_uint(bv1.y));
            SPLAT2(bs2[6], __float_as_uint(bv1.z));
            SPLAT2(bs2[7], __float_as_uint(bv1.w));
            #pragma unroll
            for (int i = 0; i < 4; i++)
                #pragma unroll
                for (int j = 0; j < 8; j++)
                    FMA2(acc2[i][j], ap[i], bs2[j]);
        }
        if (s + 1 < NST) {
            const int nb = buf ^ 1;
            __syncthreads();
            const int kb = akq * 4;
            As[nb][kb+0][arow]    = pa0.x; As[nb][kb+1][arow]    = pa0.y;
            As[nb][kb+2][arow]    = pa0.z; As[nb][kb+3][arow]    = pa0.w;
            As[nb][kb+0][64+arow] = pa1.x; As[nb][kb+1][64+arow] = pa1.y;
            As[nb][kb+2][64+arow] = pa1.z; As[nb][kb+3][64+arow] = pa1.w;
            CP_WAIT0();
            __syncthreads();
        }
    }

    #pragma unroll
    for (int i2 = 0; i2 < 4; i2++) {
        const int mrow = bm + ((i2 < 2) ? (ty*4 + i2*2) : (64 + ty*4 + (i2-2)*2));
        const int n0 = tx*4, n1 = 64 + tx*4;
        float* r0 = out + (size_t)mrow * NTOT + bn;
        float* r1 = out + (size_t)(mrow+1) * NTOT + bn;
        float4 lo0, lo1, hi0, hi1;
        lo0.x = lo_f(acc2[i2][0]) + bsm[n0+0]; hi0.x = hi_f(acc2[i2][0]) + bsm[n0+0];
        lo0.y = lo_f(acc2[i2][1]) + bsm[n0+1]; hi0.y = hi_f(acc2[i2][1]) + bsm[n0+1];
        lo0.z = lo_f(acc2[i2][2]) + bsm[n0+2]; hi0.z = hi_f(acc2[i2][2]) + bsm[n0+2];
        lo0.w = lo_f(acc2[i2][3]) + bsm[n0+3]; hi0.w = hi_f(acc2[i2][3]) + bsm[n0+3];
        lo1.x = lo_f(acc2[i2][4]) + bsm[n1+0]; hi1.x = hi_f(acc2[i2][4]) + bsm[n1+0];
        lo1.y = lo_f(acc2[i2][5]) + bsm[n1+1]; hi1.y = hi_f(acc2[i2][5]) + bsm[n1+1];
        lo1.z = lo_f(acc2[i2][6]) + bsm[n1+2]; hi1.z = hi_f(acc2[i2][6]) + bsm[n1+2];
        lo1.w = lo_f(acc2[i2][7]) + bsm[n1+3]; hi1.w = hi_f(acc2[i2][7]) + bsm[n1+3];
        *(float4*)(r0 + n0) = lo0;
        *(float4*)(r0 + n1) = lo1;
        *(float4*)(r1 + n0) = hi0;
        *(float4*)(r1 + n1) = hi1;
    }
}

// ==================== norm + hash ====================
__global__ void __launch_bounds__(128) norm_hash_kernel(const float* __restrict__ hw)
{
    int tb = blockIdx.x;
    int t = tb >> 1, b = tb & 1;
    const float* row = g_qf + tb*EE;
    int tid = threadIdx.x, lane = tid & 31, wp = tid >> 5;

    float ss = 0.f;
    for (int i = tid; i < EE; i += 128) { float x = row[i]; ss += x*x; }
    #pragma unroll
    for (int o = 16; o; o >>= 1) ss += __shfl_xor_sync(0xffffffffu, ss, o);
    __shared__ float wred[4];
    if (lane == 0) wred[wp] = ss;
    __syncthreads();
    if (tid == 0) g_invnorm[tb] = 1.0f / sqrtf(wred[0]+wred[1]+wred[2]+wred[3]);

    __shared__ float s_lin[64];
    for (int i = 0; i < 16; i++) {
        int co = wp*16 + i;
        int n = co & 3, h = (co >> 2) & 7, r = co >> 5;
        float s = 0.f;
        const float* x = row + h*DD;
        const float* w = hw + ((r*HH + h)*DD)*4 + n;
        for (int d = lane; d < DD; d += 32) s += x[d] * w[d*4];
        #pragma unroll
        for (int o = 16; o; o >>= 1) s += __shfl_xor_sync(0xffffffffu, s, o);
        if (lane == 0) s_lin[co] = s;
    }
    __syncthreads();
    if (tid < 16) {
        int r = tid >> 3, h = tid & 7;
        const float* L = s_lin + (r*8 + h)*4;
        float best = L[0]; int bi = 0;
        #pragma unroll
        for (int j = 1; j < 8; j++) {
            float v = (j < 4) ? L[j] : -L[j-4];
            if (v > best) { best = v; bi = j; }
        }
        g_hash[((b*RR + r)*HH + h)*TT + t] = bi;
    }
}

// ==================== stable counting sort ====================
__global__ void __launch_bounds__(256) sort_kernel()
{
    int brh = blockIdx.x;
    const int* hs = g_hash + brh*TT;
    int* pp = g_perm + brh*TT;
    int* iv = g_inv  + brh*TT;
    __shared__ int hist[256][8];
    __shared__ int binbase[8];
    int tid = threadIdx.x;
    int base = tid*8;
    int myh[8];
    int loc[8] = {0,0,0,0,0,0,0,0};
    #pragma unroll
    for (int i = 0; i < 8; i++) { int v = hs[base+i]; myh[i] = v; loc[v]++; }
    #pragma unroll
    for (int v = 0; v < 8; v++) hist[tid][v] = loc[v];
    __syncthreads();
    if (tid < 8) {
        int s = 0;
        for (int j = 0; j < 256; j++) { int c = hist[j][tid]; hist[j][tid] = s; s += c; }
        binbase[tid] = s;
    }
    __syncthreads();
    if (tid == 0) {
        int s = 0;
        for (int v = 0; v < 8; v++) { int t0 = binbase[v]; binbase[v] = s; s += t0; }
    }
    __syncthreads();
    int off[8];
    #pragma unroll
    for (int v = 0; v < 8; v++) off[v] = binbase[v] + hist[tid][v];
    #pragma unroll
    for (int i = 0; i < 8; i++) {
        int v = myh[i];
        int pos = off[v]++;
        pp[pos] = base + i;
        iv[base + i] = pos;
    }
}

// ==================== chunked LSH attention (raw-k cp.async, k-side norm) ====================
// Block = (b, r, h, cg), cg = group of 2 consecutive chunks. Window = 4 chunks (128 rows).
// k_s holds RAW g_qf rows (cp.async). Reference math: q = qf*scale, k = qf*kinv
//   => score = rawdot * scale * kinv_k   (NO q-side factor; softmax is not scale-invariant)
#define QS 132
#define PS 100
#define ATTN_SMEM_BYTES (128*QS*4)   // 67584

__global__ void __launch_bounds__(256, 3) attn_kernel()
{
    extern __shared__ float sm[];
    float* k_s = sm;                 // 128 x 132 (raw qf rows)
    float* p_s = sm;                 // aliases k_s after QK: 64 x 100
    __shared__ int s_kid[128], s_kh[128], s_ck[256];
    __shared__ float s_kinv[128];
    __shared__ u64 s_vp[128];        // V row pointers
    __shared__ u64 s_qp[128];        // qf row pointers (for cp.async fill)

    int bid = blockIdx.x;
    int cg = bid & 31;
    int h = (bid >> 5) & 7;
    int r = (bid >> 8) & 1;
    int b = bid >> 9;
    int brh = (b*RR + r)*HH + h;
    const int* pp = g_perm + brh*TT;
    int tid = threadIdx.x, lane = tid & 31, wp = tid >> 5;

    if (tid < 128) {
        int wc = (cg*2 + (tid >> 5) + CC - 1) & (CC - 1);
        int kid = pp[wc*32 + (tid & 31)];
        s_kid[tid] = kid;
        s_kh[tid] = g_hash[brh*TT + kid];
        s_kinv[tid] = g_invnorm[kid*BB + b];
        s_ck[tid*2+0] = g_inv[((b*RR+0)*HH+h)*TT + kid] >> 5;
        s_ck[tid*2+1] = g_inv[((b*RR+1)*HH+h)*TT + kid] >> 5;
        size_t rowoff = (size_t)kid*(BB*EE) + (size_t)b*EE + h*DD;
        s_vp[tid] = (u64)(g_vf + rowoff);
        s_qp[tid] = (u64)(g_qf + rowoff);
    }
    __syncthreads();

    // fill raw k tile via cp.async: 128 rows x 32 x 16B
    {
        uint32_t ksb = smem_u32(k_s);
        for (int idx = tid; idx < 128*32; idx += 256) {
            int j = idx >> 5, d4 = idx & 31;
            cp_async16(ksb + (uint32_t)(j*QS + d4*4)*4u, (const float*)s_qp[j] + d4*4);
        }
        CP_COMMIT();
        CP_WAIT0();
    }
    __syncthreads();

    const int kb = (wp >> 2) * 32;   // 0 or 32
    const int l0 = wp * 8;           // q rows: window rows 32+l0 .. 32+l0+7

    // ---------- QK^T (packed along d), raw dots
    u64 acc2[8][3];
    #pragma unroll
    for (int i = 0; i < 8; i++) { acc2[i][0]=0ull; acc2[i][1]=0ull; acc2[i][2]=0ull; }
    {
        const float* kp0 = k_s + (kb + lane)*QS;
        const float* kp1 = kp0 + 32*QS;
        const float* kp2 = kp0 + 64*QS;
        const float* qp  = k_s + (32 + l0)*QS;
        #pragma unroll 2
        for (int d4 = 0; d4 < 32; d4++) {
            ulonglong2 k0 = *(const ulonglong2*)(kp0 + d4*4);
            ulonglong2 k1 = *(const ulonglong2*)(kp1 + d4*4);
            ulonglong2 k2 = *(const ulonglong2*)(kp2 + d4*4);
            #pragma unroll
            for (int i = 0; i < 8; i++) {
                ulonglong2 qv = *(const ulonglong2*)(qp + i*QS + d4*4);
                FMA2(acc2[i][0], qv.x, k0.x); FMA2(acc2[i][0], qv.y, k0.y);
                FMA2(acc2[i][1], qv.x, k1.x); FMA2(acc2[i][1], qv.y, k1.y);
                FMA2(acc2[i][2], qv.x, k2.x); FMA2(acc2[i][2], qv.y, k2.y);
            }
        }
    }
    float acc[8][3];
    #pragma unroll
    for (int i = 0; i < 8; i++)
        #pragma unroll
        for (int mi = 0; mi < 3; mi++)
            acc[i][mi] = lo_f(acc2[i][mi]) + hi_f(acc2[i][mi]);

    // ---------- masks + dup correction + softmax (k-side norm only)
    const float scale = 0.08838834764831845f;  // 128^-0.5
    {
        int khv[3], kidv[3], ck0[3], ck1[3];
        float kf[3];
        #pragma unroll
        for (int mi = 0; mi < 3; mi++) {
            int m = kb + mi*32 + lane;
            khv[mi] = s_kh[m]; kidv[mi] = s_kid[m];
            ck0[mi] = s_ck[m*2+0]; ck1[mi] = s_ck[m*2+1];
            kf[mi] = scale * s_kinv[m];   // score factor: scale * kinv_k
        }
        #pragma unroll
        for (int i = 0; i < 8; i++) {
            int row = 32 + l0 + i;
            int qh = s_kh[row], qid = s_kid[row];
            int cq0 = s_ck[row*2], cq1 = s_ck[row*2+1];
            #pragma unroll
            for (int mi = 0; mi < 3; mi++) {
                float s = acc[i][mi] * kf[mi];
                if (qh != khv[mi])   s -= 1.0e16f;
                if (qid == kidv[mi]) s -= 1.0e8f;
                int d0 = (ck0[mi] - cq0) & (CC-1);
                int d1 = (ck1[mi] - cq1) & (CC-1);
                int dup = ((d0 <= 1) | (d0 == CC-1)) + ((d1 <= 1) | (d1 == CC-1));
                if (dup == 2) s -= 0.6931471805599453f;
                acc[i][mi] = s;
            }
            float mx = fmaxf(acc[i][0], fmaxf(acc[i][1], acc[i][2]));
            #pragma unroll
            for (int o = 16; o; o >>= 1) mx = fmaxf(mx, __shfl_xor_sync(0xffffffffu, mx, o));
            float p0 = __expf(acc[i][0]-mx), p1 = __expf(acc[i][1]-mx), p2 = __expf(acc[i][2]-mx);
            float sum = p0 + p1 + p2;
            #pragma unroll
            for (int o = 16; o; o >>= 1) sum += __shfl_xor_sync(0xffffffffu, sum, o);
            float rinv = 1.0f / sum;
            acc[i][0] = p0*rinv; acc[i][1] = p1*rinv; acc[i][2] = p2*rinv;
            if (lane == 0) g_z[((r*BB + b)*HH + h)*TT + qid] = __logf(sum) + mx;
        }
    }
    __syncthreads();   // all QK reads of k_s done

    #pragma unroll
    for (int i = 0; i < 8; i++) {
        float* pr = p_s + (l0 + i)*PS;
        pr[lane]      = acc[i][0];
        pr[32 + lane] = acc[i][1];
        pr[64 + lane] = acc[i][2];
    }
    __syncthreads();

    // ---------- P @ V : V via precomputed row pointers (L1/L2-resident)
    {
        const int dbase = lane*4;
        u64 o01[8], o23[8];
        #pragma unroll
        for (int i = 0; i < 8; i++) { o01[i]=0ull; o23[i]=0ull; }
        #pragma unroll 2
        for (int m4 = 0; m4 < 24; m4++) {
            int m0 = kb + m4*4;
            ulonglong2 v0 = *(const ulonglong2*)((const float*)s_vp[m0+0] + dbase);
            ulonglong2 v1 = *(const ulonglong2*)((const float*)s_vp[m0+1] + dbase);
            ulonglong2 v2 = *(const ulonglong2*)((const float*)s_vp[m0+2] + dbase);
            ulonglong2 v3 = *(const ulonglong2*)((const float*)s_vp[m0+3] + dbase);
            #pragma unroll
            for (int i = 0; i < 8; i++) {
                float4 pv = *(const float4*)&p_s[(l0+i)*PS + m4*4];
                u64 s0, s1, s2, s3;
                SPLAT2(s0, __float_as_uint(pv.x));
                SPLAT2(s1, __float_as_uint(pv.y));
                SPLAT2(s2, __float_as_uint(pv.z));
                SPLAT2(s3, __float_as_uint(pv.w));
                FMA2(o01[i], s0, v0.x); FMA2(o23[i], s0, v0.y);
                FMA2(o01[i], s1, v1.x); FMA2(o23[i], s1, v1.y);
                FMA2(o01[i], s2, v2.x); FMA2(o23[i], s2, v2.y);
                FMA2(o01[i], s3, v3.x); FMA2(o23[i], s3, v3.y);
            }
        }
        #pragma unroll
        for (int i = 0; i < 8; i++) {
            int qid = s_kid[32 + l0 + i];
            float* op = g_o + ((size_t)((r*BB + b)*HH + h)*TT + qid)*DD + dbase;
            *(float4*)op = make_float4(lo_f(o01[i]), hi_f(o01[i]), lo_f(o23[i]), hi_f(o23[i]));
        }
    }
}

// ==================== round combination ====================
__global__ void __launch_bounds__(256) combine_kernel()
{
    int idx = blockIdx.x*256 + threadIdx.x;
    int d = idx & 127;
    int t = (idx >> 7) & 2047;
    int h = (idx >> 18) & 7;
    int b = idx >> 21;
    int zi = (b*HH + h)*TT + t;
    float z0 = g_z[zi];
    float z1 = g_z[BB*HH*TT + zi];
    float mz = fmaxf(z0, z1);
    float e0 = __expf(z0 - mz), e1 = __expf(z1 - mz);
    float winv = 1.0f / (e0 + e1);
    int oi = ((b*HH + h)*TT + t)*DD + d;
    float o0 = g_o[oi];
    float o1 = g_o[BB*HH*TT*DD + oi];
    g_ctx[(t*BB + b)*EE + h*DD + d] = (e0*o0 + e1*o1) * winv;
}

// ==================== launch ====================
extern "C" void kernel_launch(void* const* d_in, const int* in_sizes, int n_in,
                              void* d_out, int out_size)
{
    const float* query = (const float*)d_in[0];
    const float* value = (const float*)d_in[2];
    const float* Wq = (const float*)d_in[3];
    const float* bq = (const float*)d_in[4];
    const float* Wv = (const float*)d_in[5];
    const float* bv = (const float*)d_in[6];
    const float* Wo = (const float*)d_in[7];
    const float* bo = (const float*)d_in[8];
    const float* hw = (const float*)d_in[9];

    float* qf;  cudaGetSymbolAddress((void**)&qf,  g_qf);
    float* vf;  cudaGetSymbolAddress((void**)&vf,  g_vf);
    float* ctx; cudaGetSymbolAddress((void**)&ctx, g_ctx);

    cudaFuncSetAttribute(attn_kernel, cudaFuncAttributeMaxDynamicSharedMemorySize, ATTN_SMEM_BYTES);

    dim3 gqv(NTOT/128, (TT*BB)/128, 2);   // fused Wq + Wv projections
    dim3 go (NTOT/128, (TT*BB)/128, 1);   // Wo projection

    sgemm_kernel<<<gqv, 256>>>(query, Wq, bq, qf, value, Wv, bv, vf);
    norm_hash_kernel<<<TT*BB, 128>>>(hw);
    sort_kernel<<<BB*RR*HH, 256>>>();
    attn_kernel<<<BB*RR*HH*32, 256, ATTN_SMEM_BYTES>>>();
    combine_kernel<<<(BB*HH*TT*DD)/256, 256>>>();
    sgemm_kernel<<<go, 256>>>(ctx, Wo, bo, (float*)d_out,
                              ctx, Wo, bo, (float*)d_out);
}

// round 12
// speedup vs baseline: 1.3868x; 1.0404x over previous
#include <cuda_runtime.h>
#include <math.h>
#include <stdint.h>

// Problem constants
#define TT 2048
#define BB 2
#define EE 1024
#define HH 8
#define DD 128
#define RR 2
#define CHUNKC 32
#define CC (TT/CHUNKC)   // 64
#define KTOT 1024
#define NTOT 1024

typedef unsigned long long u64;

// packed f32x2 helpers (sm_100+ PTX; ptxas never auto-fuses these)
#define FMA2(acc, x, y) \
    asm("fma.rn.f32x2 %0, %1, %2, %0;" : "+l"(acc) : "l"(x), "l"(y))
#define SPLAT2(d, s) \
    asm("mov.b64 %0, {%1, %1};" : "=l"(d) : "r"(s))

__device__ __forceinline__ float lo_f(u64 v) { return __uint_as_float((uint32_t)v); }
__device__ __forceinline__ float hi_f(u64 v) { return __uint_as_float((uint32_t)(v >> 32)); }

__device__ __forceinline__ uint32_t smem_u32(const void* p) {
    uint32_t a;
    asm("{ .reg .u64 t; cvta.to.shared.u64 t, %1; cvt.u32.u64 %0, t; }" : "=r"(a) : "l"(p));
    return a;
}
__device__ __forceinline__ void cp_async16(uint32_t smem_addr, const void* gptr) {
    asm volatile("cp.async.ca.shared.global [%0], [%1], 16;" :: "r"(smem_addr), "l"(gptr));
}
#define CP_COMMIT() asm volatile("cp.async.commit_group;" ::: "memory")
#define CP_WAIT0()  asm volatile("cp.async.wait_group 0;" ::: "memory")

// -------------------- device scratch --------------------
__device__ float g_qf[TT*BB*EE];
__device__ float g_vf[TT*BB*EE];
__device__ float g_ctx[TT*BB*EE];
__device__ float g_invnorm[TT*BB];
__device__ int   g_hash[BB*RR*HH*TT];
__device__ int   g_perm[BB*RR*HH*TT];
__device__ int   g_inv [BB*RR*HH*TT];
__device__ float g_o[RR*BB*HH*TT*DD];
__device__ float g_z[RR*BB*HH*TT];

// ==================== exact-fp32 SGEMM (f32x2 + cp.async B): out = A @ W + bias ====================
#define KS 16
#define NST (KTOT/KS)   // 64

__global__ void __launch_bounds__(256, 2) sgemm_kernel(
    const float* __restrict__ A0, const float* __restrict__ W0,
    const float* __restrict__ b0, float* __restrict__ o0,
    const float* __restrict__ A1, const float* __restrict__ W1,
    const float* __restrict__ b1, float* __restrict__ o1)
{
    const float* A    = blockIdx.z ? A1 : A0;
    const float* W    = blockIdx.z ? W1 : W0;
    const float* bias = blockIdx.z ? b1 : b0;
    float*       out  = blockIdx.z ? o1 : o0;

    __shared__ __align__(16) float As[2][KS][132];
    __shared__ __align__(16) float Bs[2][KS][128];
    __shared__ float bsm[128];

    const int tid = threadIdx.x;
    const int bm = blockIdx.y * 128;
    const int bn = blockIdx.x * 128;
    const int tx = tid & 15;
    const int ty = tid >> 4;

    if (tid < 128) bsm[tid] = bias[bn + tid];

    const int arow = tid >> 2;
    const int akq  = tid & 3;
    const int bkr = tid >> 5;
    const int bn4 = tid & 31;

    const float* Ap0 = A + (size_t)(bm + arow) * KTOT + akq * 4;
    const float* Ap1 = A + (size_t)(bm + 64 + arow) * KTOT + akq * 4;
    const float* Wp0 = W + (size_t)bkr * NTOT + bn + bn4 * 4;
    const float* Wp1 = W + (size_t)(8 + bkr) * NTOT + bn + bn4 * 4;

    const uint32_t bs_a0 = smem_u32(&Bs[0][bkr][bn4*4]);
    const uint32_t bs_a1 = smem_u32(&Bs[0][8+bkr][bn4*4]);
    const uint32_t bs_b0 = smem_u32(&Bs[1][bkr][bn4*4]);
    const uint32_t bs_b1 = smem_u32(&Bs[1][8+bkr][bn4*4]);

    float4 pa0, pa1;
    u64 acc2[4][8];
    #pragma unroll
    for (int i = 0; i < 4; i++)
        #pragma unroll
        for (int j = 0; j < 8; j++) acc2[i][j] = 0ull;

    pa0 = *(const float4*)(Ap0);
    pa1 = *(const float4*)(Ap1);
    cp_async16(bs_a0, Wp0);
    cp_async16(bs_a1, Wp1);
    CP_COMMIT();
    {
        const int kb = akq * 4;
        As[0][kb+0][arow]    = pa0.x; As[0][kb+1][arow]    = pa0.y;
        As[0][kb+2][arow]    = pa0.z; As[0][kb+3][arow]    = pa0.w;
        As[0][kb+0][64+arow] = pa1.x; As[0][kb+1][64+arow] = pa1.y;
        As[0][kb+2][64+arow] = pa1.z; As[0][kb+3][64+arow] = pa1.w;
    }
    CP_WAIT0();
    __syncthreads();

    for (int s = 0; s < NST; s++) {
        const int buf = s & 1;
        if (s + 1 < NST) {
            const size_t ko = (size_t)(s + 1) * KS;
            pa0 = *(const float4*)(Ap0 + ko);
            pa1 = *(const float4*)(Ap1 + ko);
            cp_async16(buf ? bs_a0 : bs_b0, Wp0 + ko * NTOT);
            cp_async16(buf ? bs_a1 : bs_b1, Wp1 + ko * NTOT);
            CP_COMMIT();
        }
        #pragma unroll
        for (int k = 0; k < KS; k++) {
            ulonglong2 a0 = *(const ulonglong2*)&As[buf][k][ty*4];
            ulonglong2 a1 = *(const ulonglong2*)&As[buf][k][64 + ty*4];
            float4 bv0 = *(const float4*)&Bs[buf][k][tx*4];
            float4 bv1 = *(const float4*)&Bs[buf][k][64 + tx*4];
            u64 ap[4] = {a0.x, a0.y, a1.x, a1.y};
            u64 bs2[8];
            SPLAT2(bs2[0], __float_as_uint(bv0.x));
            SPLAT2(bs2[1], __float_as_uint(bv0.y));
            SPLAT2(bs2[2], __float_as_uint(bv0.z));
            SPLAT2(bs2[3], __float_as_uint(bv0.w));
            SPLAT2(bs2[4], __float_as_uint(bv1.x));
            SPLAT2(bs2[5], __float_as_uint(bv1.y));
            SPLAT2(bs2[6], __float_as_uint(bv1.z));
            SPLAT2(bs2[7], __float_as_uint(bv1.w));
            #pragma unroll
            for (int i = 0; i < 4; i++)
                #pragma unroll
                for (int j = 0; j < 8; j++)
                    FMA2(acc2[i][j], ap[i], bs2[j]);
        }
        if (s + 1 < NST) {
            const int nb = buf ^ 1;
            __syncthreads();
            const int kb = akq * 4;
            As[nb][kb+0][arow]    = pa0.x; As[nb][kb+1][arow]    = pa0.y;
            As[nb][kb+2][arow]    = pa0.z; As[nb][kb+3][arow]    = pa0.w;
            As[nb][kb+0][64+arow] = pa1.x; As[nb][kb+1][64+arow] = pa1.y;
            As[nb][kb+2][64+arow] = pa1.z; As[nb][kb+3][64+arow] = pa1.w;
            CP_WAIT0();
            __syncthreads();
        }
    }

    #pragma unroll
    for (int i2 = 0; i2 < 4; i2++) {
        const int mrow = bm + ((i2 < 2) ? (ty*4 + i2*2) : (64 + ty*4 + (i2-2)*2));
        const int n0 = tx*4, n1 = 64 + tx*4;
        float* r0 = out + (size_t)mrow * NTOT + bn;
        float* r1 = out + (size_t)(mrow+1) * NTOT + bn;
        float4 lo0, lo1, hi0, hi1;
        lo0.x = lo_f(acc2[i2][0]) + bsm[n0+0]; hi0.x = hi_f(acc2[i2][0]) + bsm[n0+0];
        lo0.y = lo_f(acc2[i2][1]) + bsm[n0+1]; hi0.y = hi_f(acc2[i2][1]) + bsm[n0+1];
        lo0.z = lo_f(acc2[i2][2]) + bsm[n0+2]; hi0.z = hi_f(acc2[i2][2]) + bsm[n0+2];
        lo0.w = lo_f(acc2[i2][3]) + bsm[n0+3]; hi0.w = hi_f(acc2[i2][3]) + bsm[n0+3];
        lo1.x = lo_f(acc2[i2][4]) + bsm[n1+0]; hi1.x = hi_f(acc2[i2][4]) + bsm[n1+0];
        lo1.y = lo_f(acc2[i2][5]) + bsm[n1+1]; hi1.y = hi_f(acc2[i2][5]) + bsm[n1+1];
        lo1.z = lo_f(acc2[i2][6]) + bsm[n1+2]; hi1.z = hi_f(acc2[i2][6]) + bsm[n1+2];
        lo1.w = lo_f(acc2[i2][7]) + bsm[n1+3]; hi1.w = hi_f(acc2[i2][7]) + bsm[n1+3];
        *(float4*)(r0 + n0) = lo0;
        *(float4*)(r0 + n1) = lo1;
        *(float4*)(r1 + n0) = hi0;
        *(float4*)(r1 + n1) = hi1;
    }
}

// ==================== norm + hash (register-serial dots, no reductions) ====================
// Block = 16 consecutive tb tokens, 256 threads.
// Phase A: 8 warps x 2 rows -> sumsq/invnorm. Phase B: thread = (row 0..15, rh 0..15),
// computes 4 hash dots serially in registers; argmax over [lin, -lin].
__global__ void __launch_bounds__(256) norm_hash_kernel(const float* __restrict__ hw)
{
    __shared__ float w_s[RR*HH*DD*4];   // 8192 floats = 32 KB
    int tid = threadIdx.x, lane = tid & 31, wp = tid >> 5;
    int tb0 = blockIdx.x * 16;

    // stage hash_w
    #pragma unroll
    for (int i = 0; i < 8; i++)
        ((float4*)w_s)[tid + i*256] = ((const float4*)hw)[tid + i*256];

    // Phase A: sumsq per row (warp wp owns rows wp*2, wp*2+1)
    #pragma unroll
    for (int rr = 0; rr < 2; rr++) {
        int tb = tb0 + wp*2 + rr;
        const float4* row = (const float4*)(g_qf + (size_t)tb*EE);
        float ss = 0.f;
        #pragma unroll
        for (int i = 0; i < 8; i++) {
            float4 v = row[lane + i*32];
            ss += v.x*v.x + v.y*v.y + v.z*v.z + v.w*v.w;
        }
        #pragma unroll
        for (int o = 16; o; o >>= 1) ss += __shfl_xor_sync(0xffffffffu, ss, o);
        if (lane == 0) g_invnorm[tb] = 1.0f / sqrtf(ss);
    }
    __syncthreads();

    // Phase B: per-thread serial dots
    int row = tid & 15, rh = tid >> 4;
    int r = rh >> 3, h = rh & 7;
    int tb = tb0 + row;
    int t = tb >> 1, b = tb & 1;
    const float4* x = (const float4*)(g_qf + (size_t)tb*EE + h*DD);
    const float4* wseg = (const float4*)(w_s + (r*HH + h)*DD*4);

    float l0 = 0.f, l1 = 0.f, l2 = 0.f, l3 = 0.f;
    #pragma unroll 8
    for (int d4 = 0; d4 < 32; d4++) {
        float4 xv = x[d4];
        float4 w0 = wseg[d4*4+0], w1 = wseg[d4*4+1];
        float4 w2 = wseg[d4*4+2], w3 = wseg[d4*4+3];
        l0 += xv.x*w0.x + xv.y*w1.x + xv.z*w2.x + xv.w*w3.x;
        l1 += xv.x*w0.y + xv.y*w1.y + xv.z*w2.y + xv.w*w3.y;
        l2 += xv.x*w0.z + xv.y*w1.z + xv.z*w2.z + xv.w*w3.z;
        l3 += xv.x*w0.w + xv.y*w1.w + xv.z*w2.w + xv.w*w3.w;
    }
    float best = l0; int bi = 0;
    if (l1 > best) { best = l1; bi = 1; }
    if (l2 > best) { best = l2; bi = 2; }
    if (l3 > best) { best = l3; bi = 3; }
    if (-l0 > best) { best = -l0; bi = 4; }
    if (-l1 > best) { best = -l1; bi = 5; }
    if (-l2 > best) { best = -l2; bi = 6; }
    if (-l3 > best) { best = -l3; bi = 7; }
    g_hash[((b*RR + r)*HH + h)*TT + t] = bi;
}

// ==================== stable counting sort (warp-parallel scan) ====================
__global__ void __launch_bounds__(256) sort_kernel()
{
    int brh = blockIdx.x;
    const int* hs = g_hash + brh*TT;
    int* pp = g_perm + brh*TT;
    int* iv = g_inv  + brh*TT;
    __shared__ int hist[256][9];     // padded: conflict-free column scans
    __shared__ int btot[8], binbase[8];
    int tid = threadIdx.x, lane = tid & 31, wp = tid >> 5;
    int base = tid*8;
    int myh[8];
    int loc[8] = {0,0,0,0,0,0,0,0};
    #pragma unroll
    for (int i = 0; i < 8; i++) { int v = hs[base+i]; myh[i] = v; loc[v]++; }
    #pragma unroll
    for (int v = 0; v < 8; v++) hist[tid][v] = loc[v];
    __syncthreads();
    // warp wp scans bin wp across the 256 thread-entries
    {
        int carry = 0;
        #pragma unroll
        for (int c = 0; c < 8; c++) {
            int v = hist[c*32 + lane][wp];
            int s = v;
            #pragma unroll
            for (int o = 1; o < 32; o <<= 1) {
                int n = __shfl_up_sync(0xffffffffu, s, o);
                if (lane >= o) s += n;
            }
            hist[c*32 + lane][wp] = carry + s - v;   // exclusive
            carry += __shfl_sync(0xffffffffu, s, 31);
        }
        if (lane == 0) btot[wp] = carry;
    }
    __syncthreads();
    if (tid == 0) {
        int s = 0;
        #pragma unroll
        for (int v = 0; v < 8; v++) { binbase[v] = s; s += btot[v]; }
    }
    __syncthreads();
    int off[8];
    #pragma unroll
    for (int v = 0; v < 8; v++) off[v] = binbase[v] + hist[tid][v];
    #pragma unroll
    for (int i = 0; i < 8; i++) {
        int v = myh[i];
        int pos = off[v]++;
        pp[pos] = base + i;
        iv[base + i] = pos;
    }
}

// ==================== chunked LSH attention (raw-k cp.async, k-side norm) ====================
#define QS 132
#define PS 100
#define ATTN_SMEM_BYTES (128*QS*4)   // 67584

__global__ void __launch_bounds__(256, 3) attn_kernel()
{
    extern __shared__ float sm[];
    float* k_s = sm;                 // 128 x 132 (raw qf rows)
    float* p_s = sm;                 // aliases k_s after QK: 64 x 100
    __shared__ int s_kid[128], s_kh[128], s_ck[256];
    __shared__ float s_kinv[128];
    __shared__ u64 s_vp[128];
    __shared__ u64 s_qp[128];

    int bid = blockIdx.x;
    int cg = bid & 31;
    int h = (bid >> 5) & 7;
    int r = (bid >> 8) & 1;
    int b = bid >> 9;
    int brh = (b*RR + r)*HH + h;
    const int* pp = g_perm + brh*TT;
    int tid = threadIdx.x, lane = tid & 31, wp = tid >> 5;

    if (tid < 128) {
        int wc = (cg*2 + (tid >> 5) + CC - 1) & (CC - 1);
        int kid = pp[wc*32 + (tid & 31)];
        s_kid[tid] = kid;
        s_kh[tid] = g_hash[brh*TT + kid];
        s_kinv[tid] = g_invnorm[kid*BB + b];
        s_ck[tid*2+0] = g_inv[((b*RR+0)*HH+h)*TT + kid] >> 5;
        s_ck[tid*2+1] = g_inv[((b*RR+1)*HH+h)*TT + kid] >> 5;
        size_t rowoff = (size_t)kid*(BB*EE) + (size_t)b*EE + h*DD;
        s_vp[tid] = (u64)(g_vf + rowoff);
        s_qp[tid] = (u64)(g_qf + rowoff);
    }
    __syncthreads();

    {
        uint32_t ksb = smem_u32(k_s);
        for (int idx = tid; idx < 128*32; idx += 256) {
            int j = idx >> 5, d4 = idx & 31;
            cp_async16(ksb + (uint32_t)(j*QS + d4*4)*4u, (const float*)s_qp[j] + d4*4);
        }
        CP_COMMIT();
        CP_WAIT0();
    }
    __syncthreads();

    const int kb = (wp >> 2) * 32;
    const int l0 = wp * 8;

    u64 acc2[8][3];
    #pragma unroll
    for (int i = 0; i < 8; i++) { acc2[i][0]=0ull; acc2[i][1]=0ull; acc2[i][2]=0ull; }
    {
        const float* kp0 = k_s + (kb + lane)*QS;
        const float* kp1 = kp0 + 32*QS;
        const float* kp2 = kp0 + 64*QS;
        const float* qp  = k_s + (32 + l0)*QS;
        #pragma unroll 2
        for (int d4 = 0; d4 < 32; d4++) {
            ulonglong2 k0 = *(const ulonglong2*)(kp0 + d4*4);
            ulonglong2 k1 = *(const ulonglong2*)(kp1 + d4*4);
            ulonglong2 k2 = *(const ulonglong2*)(kp2 + d4*4);
            #pragma unroll
            for (int i = 0; i < 8; i++) {
                ulonglong2 qv = *(const ulonglong2*)(qp + i*QS + d4*4);
                FMA2(acc2[i][0], qv.x, k0.x); FMA2(acc2[i][0], qv.y, k0.y);
                FMA2(acc2[i][1], qv.x, k1.x); FMA2(acc2[i][1], qv.y, k1.y);
                FMA2(acc2[i][2], qv.x, k2.x); FMA2(acc2[i][2], qv.y, k2.y);
            }
        }
    }
    float acc[8][3];
    #pragma unroll
    for (int i = 0; i < 8; i++)
        #pragma unroll
        for (int mi = 0; mi < 3; mi++)
            acc[i][mi] = lo_f(acc2[i][mi]) + hi_f(acc2[i][mi]);

    const float scale = 0.08838834764831845f;  // 128^-0.5
    {
        int khv[3], kidv[3], ck0[3], ck1[3];
        float kf[3];
        #pragma unroll
        for (int mi = 0; mi < 3; mi++) {
            int m = kb + mi*32 + lane;
            khv[mi] = s_kh[m]; kidv[mi] = s_kid[m];
            ck0[mi] = s_ck[m*2+0]; ck1[mi] = s_ck[m*2+1];
            kf[mi] = scale * s_kinv[m];
        }
        #pragma unroll
        for (int i = 0; i < 8; i++) {
            int row = 32 + l0 + i;
            int qh = s_kh[row], qid = s_kid[row];
            int cq0 = s_ck[row*2], cq1 = s_ck[row*2+1];
            #pragma unroll
            for (int mi = 0; mi < 3; mi++) {
                float s = acc[i][mi] * kf[mi];
                if (qh != khv[mi])   s -= 1.0e16f;
                if (qid == kidv[mi]) s -= 1.0e8f;
                int d0 = (ck0[mi] - cq0) & (CC-1);
                int d1 = (ck1[mi] - cq1) & (CC-1);
                int dup = ((d0 <= 1) | (d0 == CC-1)) + ((d1 <= 1) | (d1 == CC-1));
                if (dup == 2) s -= 0.6931471805599453f;
                acc[i][mi] = s;
            }
            float mx = fmaxf(acc[i][0], fmaxf(acc[i][1], acc[i][2]));
            #pragma unroll
            for (int o = 16; o; o >>= 1) mx = fmaxf(mx, __shfl_xor_sync(0xffffffffu, mx, o));
            float p0 = __expf(acc[i][0]-mx), p1 = __expf(acc[i][1]-mx), p2 = __expf(acc[i][2]-mx);
            float sum = p0 + p1 + p2;
            #pragma unroll
            for (int o = 16; o; o >>= 1) sum += __shfl_xor_sync(0xffffffffu, sum, o);
            float rinv = 1.0f / sum;
            acc[i][0] = p0*rinv; acc[i][1] = p1*rinv; acc[i][2] = p2*rinv;
            if (lane == 0) g_z[((r*BB + b)*HH + h)*TT + qid] = __logf(sum) + mx;
        }
    }
    __syncthreads();

    #pragma unroll
    for (int i = 0; i < 8; i++) {
        float* pr = p_s + (l0 + i)*PS;
        pr[lane]      = acc[i][0];
        pr[32 + lane] = acc[i][1];
        pr[64 + lane] = acc[i][2];
    }
    __syncthreads();

    {
        const int dbase = lane*4;
        u64 o01[8], o23[8];
        #pragma unroll
        for (int i = 0; i < 8; i++) { o01[i]=0ull; o23[i]=0ull; }
        #pragma unroll 2
        for (int m4 = 0; m4 < 24; m4++) {
            int m0 = kb + m4*4;
            ulonglong2 v0 = *(const ulonglong2*)((const float*)s_vp[m0+0] + dbase);
            ulonglong2 v1 = *(const ulonglong2*)((const float*)s_vp[m0+1] + dbase);
            ulonglong2 v2 = *(const ulonglong2*)((const float*)s_vp[m0+2] + dbase);
            ulonglong2 v3 = *(const ulonglong2*)((const float*)s_vp[m0+3] + dbase);
            #pragma unroll
            for (int i = 0; i < 8; i++) {
                float4 pv = *(const float4*)&p_s[(l0+i)*PS + m4*4];
                u64 s0, s1, s2, s3;
                SPLAT2(s0, __float_as_uint(pv.x));
                SPLAT2(s1, __float_as_uint(pv.y));
                SPLAT2(s2, __float_as_uint(pv.z));
                SPLAT2(s3, __float_as_uint(pv.w));
                FMA2(o01[i], s0, v0.x); FMA2(o23[i], s0, v0.y);
                FMA2(o01[i], s1, v1.x); FMA2(o23[i], s1, v1.y);
                FMA2(o01[i], s2, v2.x); FMA2(o23[i], s2, v2.y);
                FMA2(o01[i], s3, v3.x); FMA2(o23[i], s3, v3.y);
            }
        }
        #pragma unroll
        for (int i = 0; i < 8; i++) {
            int qid = s_kid[32 + l0 + i];
            float* op = g_o + ((size_t)((r*BB + b)*HH + h)*TT + qid)*DD + dbase;
            *(float4*)op = make_float4(lo_f(o01[i]), hi_f(o01[i]), lo_f(o23[i]), hi_f(o23[i]));
        }
    }
}

// ==================== round combination (float4) ====================
__global__ void __launch_bounds__(256) combine_kernel()
{
    int idx = blockIdx.x*256 + threadIdx.x;   // over B*H*T*D/4 = 2^20
    int d4 = idx & 31;
    int t = (idx >> 5) & 2047;
    int h = (idx >> 16) & 7;
    int b = idx >> 19;
    int zi = (b*HH + h)*TT + t;
    float z0 = g_z[zi];
    float z1 = g_z[BB*HH*TT + zi];
    float mz = fmaxf(z0, z1);
    float e0 = __expf(z0 - mz), e1 = __expf(z1 - mz);
    float winv = 1.0f / (e0 + e1);
    float w0 = e0 * winv, w1 = e1 * winv;
    const float4* o4 = (const float4*)g_o;
    int oi = ((b*HH + h)*TT + t)*32 + d4;
    float4 v0 = o4[oi];
    float4 v1 = o4[BB*HH*TT*32 + oi];
    float4 out;
    out.x = w0*v0.x + w1*v1.x;
    out.y = w0*v0.y + w1*v1.y;
    out.z = w0*v0.z + w1*v1.z;
    out.w = w0*v0.w + w1*v1.w;
    ((float4*)g_ctx)[(t*BB + b)*256 + h*32 + d4] = out;
}

// ==================== launch ====================
extern "C" void kernel_launch(void* const* d_in, const int* in_sizes, int n_in,
                              void* d_out, int out_size)
{
    const float* query = (const float*)d_in[0];
    const float* value = (const float*)d_in[2];
    const float* Wq = (const float*)d_in[3];
    const float* bq = (const float*)d_in[4];
    const float* Wv = (const float*)d_in[5];
    const float* bv = (const float*)d_in[6];
    const float* Wo = (const float*)d_in[7];
    const float* bo = (const float*)d_in[8];
    const float* hw = (const float*)d_in[9];

    float* qf;  cudaGetSymbolAddress((void**)&qf,  g_qf);
    float* vf;  cudaGetSymbolAddress((void**)&vf,  g_vf);
    float* ctx; cudaGetSymbolAddress((void**)&ctx, g_ctx);

    cudaFuncSetAttribute(attn_kernel, cudaFuncAttributeMaxDynamicSharedMemorySize, ATTN_SMEM_BYTES);

    dim3 gqv(NTOT/128, (TT*BB)/128, 2);   // fused Wq + Wv projections
    dim3 go (NTOT/128, (TT*BB)/128, 1);   // Wo projection

    sgemm_kernel<<<gqv, 256>>>(query, Wq, bq, qf, value, Wv, bv, vf);
    norm_hash_kernel<<<(TT*BB)/16, 256>>>(hw);
    sort_kernel<<<BB*RR*HH, 256>>>();
    attn_kernel<<<BB*RR*HH*32, 256, ATTN_SMEM_BYTES>>>();
    combine_kernel<<<(BB*HH*TT*DD/4)/256, 256>>>();
    sgemm_kernel<<<go, 256>>>(ctx, Wo, bo, (float*)d_out,
                              ctx, Wo, bo, (float*)d_out);
}